// round 1
// baseline (speedup 1.0000x reference)
#include <cuda_runtime.h>
#include <cuda_bf16.h>
#include <cstddef>

#define NROWS 8192
#define DDIM  1024
#define CDIM  1000

// ---------------- scratch (static device globals; no allocations) ----------
__device__ float g_xr[(size_t)NROWS * DDIM];
__device__ float g_q [(size_t)NROWS * DDIM];
__device__ float g_k [(size_t)NROWS * DDIM];
__device__ float g_v [(size_t)NROWS * DDIM];
__device__ float g_a [(size_t)NROWS * DDIM];
__device__ float g_h [(size_t)NROWS * DDIM];
__device__ float g_s [(size_t)NROWS * NROWS];   // 268 MB scores/attn
__device__ float g_u [DDIM];                    // W_beta[0:D] + W_beta[2D:3D]
__device__ float g_w [DDIM];                    // W_beta[D:2D] - W_beta[2D:3D]

// ---------------- SGEMM NN: C = alpha*(A@B) + bias, A[M,K] B[K,Ncol] -------
// 128x128 tile, BK=8, 256 threads, 8x8 microtile (split-4 layout).
// Assumes M % 128 == 0 and K % 8 == 0. Ncol may be ragged (guarded).
__global__ __launch_bounds__(256, 2) void sgemm_nn(
    const float* __restrict__ A, const float* __restrict__ B,
    const float* __restrict__ bias, float* __restrict__ C,
    int M, int Ncol, int K, float alpha)
{
    __shared__ float As[8][128];
    __shared__ float Bs[8][128];
    const int tid = threadIdx.x;
    const int tx = tid & 15;
    const int ty = tid >> 4;
    const int row0 = blockIdx.y * 128;
    const int col0 = blockIdx.x * 128;

    const int a_row = tid >> 1;          // 0..127
    const int a_k4  = (tid & 1) * 4;     // 0 or 4
    const int b_k   = tid >> 5;          // 0..7
    const int b_c4  = (tid & 31) * 4;    // 0..124

    float acc[8][8];
#pragma unroll
    for (int i = 0; i < 8; i++)
#pragma unroll
        for (int j = 0; j < 8; j++) acc[i][j] = 0.f;

    for (int k0 = 0; k0 < K; k0 += 8) {
        // A tile: [128 rows x 8 k], stored transposed As[k][row]
        float4 av = *(const float4*)(A + (size_t)(row0 + a_row) * K + (k0 + a_k4));
        As[a_k4 + 0][a_row] = av.x; As[a_k4 + 1][a_row] = av.y;
        As[a_k4 + 2][a_row] = av.z; As[a_k4 + 3][a_row] = av.w;

        // B tile: [8 k x 128 cols]
        {
            int gc = col0 + b_c4;
            const float* bp = B + (size_t)(k0 + b_k) * Ncol + gc;
            float4 bv;
            if (gc + 3 < Ncol) {
                bv = *(const float4*)bp;
            } else {
                bv.x = (gc + 0 < Ncol) ? bp[0] : 0.f;
                bv.y = (gc + 1 < Ncol) ? bp[1] : 0.f;
                bv.z = (gc + 2 < Ncol) ? bp[2] : 0.f;
                bv.w = (gc + 3 < Ncol) ? bp[3] : 0.f;
            }
            Bs[b_k][b_c4 + 0] = bv.x; Bs[b_k][b_c4 + 1] = bv.y;
            Bs[b_k][b_c4 + 2] = bv.z; Bs[b_k][b_c4 + 3] = bv.w;
        }
        __syncthreads();

#pragma unroll
        for (int kk = 0; kk < 8; kk++) {
            float4 a0 = *(const float4*)&As[kk][ty * 4];
            float4 a1 = *(const float4*)&As[kk][64 + ty * 4];
            float4 b0 = *(const float4*)&Bs[kk][tx * 4];
            float4 b1 = *(const float4*)&Bs[kk][64 + tx * 4];
            float ar[8] = {a0.x, a0.y, a0.z, a0.w, a1.x, a1.y, a1.z, a1.w};
            float br[8] = {b0.x, b0.y, b0.z, b0.w, b1.x, b1.y, b1.z, b1.w};
#pragma unroll
            for (int i = 0; i < 8; i++)
#pragma unroll
                for (int j = 0; j < 8; j++)
                    acc[i][j] = fmaf(ar[i], br[j], acc[i][j]);
        }
        __syncthreads();
    }

#pragma unroll
    for (int i = 0; i < 8; i++) {
        int r = row0 + ((i < 4) ? (ty * 4 + i) : (64 + ty * 4 + (i - 4)));
#pragma unroll
        for (int j = 0; j < 8; j++) {
            int c = col0 + ((j < 4) ? (tx * 4 + j) : (64 + tx * 4 + (j - 4)));
            if (c < Ncol) {
                float val = alpha * acc[i][j];
                if (bias) val += bias[c];
                C[(size_t)r * Ncol + c] = val;
            }
        }
    }
}

// ---------------- SGEMM NT: C = alpha*(A @ Bt^T), A[M,K], Bt[Ncol,K] -------
// All dims multiples of tile sizes (used for QK^T: 8192x8192x1024).
__global__ __launch_bounds__(256, 2) void sgemm_nt(
    const float* __restrict__ A, const float* __restrict__ Bt,
    float* __restrict__ C, int M, int Ncol, int K, float alpha)
{
    __shared__ float As[8][128];
    __shared__ float Bs[8][128];
    const int tid = threadIdx.x;
    const int tx = tid & 15;
    const int ty = tid >> 4;
    const int row0 = blockIdx.y * 128;
    const int col0 = blockIdx.x * 128;

    const int l_row = tid >> 1;          // 0..127
    const int l_k4  = (tid & 1) * 4;     // 0 or 4

    float acc[8][8];
#pragma unroll
    for (int i = 0; i < 8; i++)
#pragma unroll
        for (int j = 0; j < 8; j++) acc[i][j] = 0.f;

    for (int k0 = 0; k0 < K; k0 += 8) {
        float4 av = *(const float4*)(A  + (size_t)(row0 + l_row) * K + (k0 + l_k4));
        As[l_k4 + 0][l_row] = av.x; As[l_k4 + 1][l_row] = av.y;
        As[l_k4 + 2][l_row] = av.z; As[l_k4 + 3][l_row] = av.w;

        float4 bv = *(const float4*)(Bt + (size_t)(col0 + l_row) * K + (k0 + l_k4));
        Bs[l_k4 + 0][l_row] = bv.x; Bs[l_k4 + 1][l_row] = bv.y;
        Bs[l_k4 + 2][l_row] = bv.z; Bs[l_k4 + 3][l_row] = bv.w;
        __syncthreads();

#pragma unroll
        for (int kk = 0; kk < 8; kk++) {
            float4 a0 = *(const float4*)&As[kk][ty * 4];
            float4 a1 = *(const float4*)&As[kk][64 + ty * 4];
            float4 b0 = *(const float4*)&Bs[kk][tx * 4];
            float4 b1 = *(const float4*)&Bs[kk][64 + tx * 4];
            float ar[8] = {a0.x, a0.y, a0.z, a0.w, a1.x, a1.y, a1.z, a1.w};
            float br[8] = {b0.x, b0.y, b0.z, b0.w, b1.x, b1.y, b1.z, b1.w};
#pragma unroll
            for (int i = 0; i < 8; i++)
#pragma unroll
                for (int j = 0; j < 8; j++)
                    acc[i][j] = fmaf(ar[i], br[j], acc[i][j]);
        }
        __syncthreads();
    }

#pragma unroll
    for (int i = 0; i < 8; i++) {
        int r = row0 + ((i < 4) ? (ty * 4 + i) : (64 + ty * 4 + (i - 4)));
#pragma unroll
        for (int j = 0; j < 8; j++) {
            int c = col0 + ((j < 4) ? (tx * 4 + j) : (64 + tx * 4 + (j - 4)));
            C[(size_t)r * Ncol + c] = alpha * acc[i][j];
        }
    }
}

// ---------------- row softmax (in place), n % 1024 == 0 --------------------
__global__ __launch_bounds__(256) void softmax_rows(float* __restrict__ S, int n)
{
    __shared__ float red[256];
    const int row = blockIdx.x;
    const int tid = threadIdx.x;
    float* p = S + (size_t)row * n;

    float m = -3.4e38f;
    for (int i = tid * 4; i < n; i += 1024) {
        float4 v = *(const float4*)&p[i];
        m = fmaxf(m, fmaxf(fmaxf(v.x, v.y), fmaxf(v.z, v.w)));
    }
    red[tid] = m; __syncthreads();
    for (int s = 128; s > 0; s >>= 1) {
        if (tid < s) red[tid] = fmaxf(red[tid], red[tid + s]);
        __syncthreads();
    }
    m = red[0]; __syncthreads();

    float sum = 0.f;
    for (int i = tid * 4; i < n; i += 1024) {
        float4 v = *(float4*)&p[i];
        v.x = __expf(v.x - m); v.y = __expf(v.y - m);
        v.z = __expf(v.z - m); v.w = __expf(v.w - m);
        *(float4*)&p[i] = v;
        sum += v.x + v.y + v.z + v.w;
    }
    red[tid] = sum; __syncthreads();
    for (int s = 128; s > 0; s >>= 1) {
        if (tid < s) red[tid] += red[tid + s];
        __syncthreads();
    }
    float inv = 1.f / red[0];

    for (int i = tid * 4; i < n; i += 1024) {
        float4 v = *(float4*)&p[i];
        v.x *= inv; v.y *= inv; v.z *= inv; v.w *= inv;
        *(float4*)&p[i] = v;
    }
}

// ---------------- beta prep: fold concat-GEMV into two D-vectors -----------
__global__ void prep_beta(const float* __restrict__ Wb)
{
    int i = blockIdx.x * 256 + threadIdx.x;
    if (i < DDIM) {
        g_u[i] = Wb[i] + Wb[2 * DDIM + i];          // multiplies a
        g_w[i] = Wb[DDIM + i] - Wb[2 * DDIM + i];   // multiplies x_r
    }
}

// ---------------- fused beta + gate: h = beta*x_r + (1-beta)*a -------------
__global__ __launch_bounds__(256) void beta_gate(
    const float* __restrict__ a, const float* __restrict__ xr,
    const float* __restrict__ b_beta, float* __restrict__ h)
{
    __shared__ float sa[DDIM];
    __shared__ float sx[DDIM];
    __shared__ float red[256];
    const int row = blockIdx.x;
    const int tid = threadIdx.x;
    const float* pa = a  + (size_t)row * DDIM;
    const float* px = xr + (size_t)row * DDIM;

    float part = 0.f;
    for (int i = tid; i < DDIM; i += 256) {
        float av = pa[i], xv = px[i];
        sa[i] = av; sx[i] = xv;
        part += av * g_u[i] + xv * g_w[i];
    }
    red[tid] = part; __syncthreads();
    for (int s = 128; s > 0; s >>= 1) {
        if (tid < s) red[tid] += red[tid + s];
        __syncthreads();
    }
    float z = red[0] + b_beta[0];
    float beta = 1.f / (1.f + __expf(-z));

    float* ph = h + (size_t)row * DDIM;
    for (int i = tid; i < DDIM; i += 256)
        ph[i] = beta * sx[i] + (1.f - beta) * sa[i];
}

// ---------------------------------------------------------------------------
extern "C" void kernel_launch(void* const* d_in, const int* in_sizes, int n_in,
                              void* d_out, int out_size)
{
    const float* x      = (const float*)d_in[0];
    const float* W_skip = (const float*)d_in[1];
    const float* b_skip = (const float*)d_in[2];
    const float* W_q    = (const float*)d_in[3];
    const float* b_q    = (const float*)d_in[4];
    const float* W_k    = (const float*)d_in[5];
    const float* b_k    = (const float*)d_in[6];
    const float* W_v    = (const float*)d_in[7];
    const float* b_v    = (const float*)d_in[8];
    const float* W_beta = (const float*)d_in[9];
    const float* b_beta = (const float*)d_in[10];
    const float* W_fc   = (const float*)d_in[11];
    const float* b_fc   = (const float*)d_in[12];
    float* out = (float*)d_out;

    float *xr, *q, *k, *v, *a, *h, *s;
    cudaGetSymbolAddress((void**)&xr, g_xr);
    cudaGetSymbolAddress((void**)&q,  g_q);
    cudaGetSymbolAddress((void**)&k,  g_k);
    cudaGetSymbolAddress((void**)&v,  g_v);
    cudaGetSymbolAddress((void**)&a,  g_a);
    cudaGetSymbolAddress((void**)&h,  g_h);
    cudaGetSymbolAddress((void**)&s,  g_s);

    dim3 blk(256);

    // projections: [8192,1024] @ [1024,1024] + bias
    dim3 gp(DDIM / 128, NROWS / 128);
    sgemm_nn<<<gp, blk>>>(x, W_skip, b_skip, xr, NROWS, DDIM, DDIM, 1.f);
    sgemm_nn<<<gp, blk>>>(x, W_q,    b_q,    q,  NROWS, DDIM, DDIM, 1.f);
    sgemm_nn<<<gp, blk>>>(x, W_k,    b_k,    k,  NROWS, DDIM, DDIM, 1.f);
    sgemm_nn<<<gp, blk>>>(x, W_v,    b_v,    v,  NROWS, DDIM, DDIM, 1.f);

    // fold W_beta (independent of attention; launch early)
    prep_beta<<<(DDIM + 255) / 256, 256>>>(W_beta);

    // scores = q @ k^T / 32
    dim3 gs(NROWS / 128, NROWS / 128);
    sgemm_nt<<<gs, blk>>>(q, k, s, NROWS, NROWS, DDIM, 0.03125f);

    // softmax rows
    softmax_rows<<<NROWS, 256>>>(s, NROWS);

    // a = attn @ v
    dim3 ga(DDIM / 128, NROWS / 128);
    sgemm_nn<<<ga, blk>>>(s, v, (const float*)nullptr, a, NROWS, DDIM, NROWS, 1.f);

    // h = beta*x_r + (1-beta)*a
    beta_gate<<<NROWS, 256>>>(a, xr, b_beta, h);

    // out = h @ W_fc + b_fc
    dim3 gf((CDIM + 127) / 128, NROWS / 128);
    sgemm_nn<<<gf, blk>>>(h, W_fc, b_fc, out, NROWS, CDIM, DDIM, 1.f);
}

// round 5
// speedup vs baseline: 2.8809x; 2.8809x over previous
#include <cuda_runtime.h>
#include <cuda_bf16.h>
#include <cstdint>
#include <cstddef>

#define NROWS 8192
#define DDIM  1024
#define CDIM  1000
#define CPAD  1024

// ---------------- scratch (static device globals; no allocations) ----------
__device__ float g_xr[(size_t)NROWS * DDIM];
__device__ float g_q [(size_t)NROWS * DDIM];
__device__ float g_k [(size_t)NROWS * DDIM];
__device__ float g_v [(size_t)NROWS * DDIM];
__device__ float g_a [(size_t)NROWS * DDIM];
__device__ float g_h [(size_t)NROWS * DDIM];
__device__ float g_s [(size_t)NROWS * NROWS];   // 268 MB scores/attn
__device__ float g_rx[(size_t)NROWS * DDIM];    // tf32-rounded x
__device__ float g_rws[(size_t)DDIM * DDIM];
__device__ float g_rwq[(size_t)DDIM * DDIM];
__device__ float g_rwk[(size_t)DDIM * DDIM];
__device__ float g_rwv[(size_t)DDIM * DDIM];
__device__ float g_rwf[(size_t)DDIM * CPAD];    // padded+rounded W_fc
__device__ float g_u [DDIM];
__device__ float g_w [DDIM];

// ---------------- helpers ---------------------------------------------------
__device__ __forceinline__ float rna_tf32(float x) {
    uint32_t u;
    asm("cvt.rna.tf32.f32 %0, %1;" : "=r"(u) : "f"(x));
    return __uint_as_float(u);
}
__device__ __forceinline__ void cp16(uint32_t s, const void* g) {
    asm volatile("cp.async.cg.shared.global [%0], [%1], 16;\n" :: "r"(s), "l"(g));
}
__device__ __forceinline__ void cp_commit() { asm volatile("cp.async.commit_group;\n"); }
__device__ __forceinline__ void cp_wait0()  { asm volatile("cp.async.wait_group 0;\n"); }

__device__ __forceinline__ void mma_tf32(float* d, const uint32_t* a, const uint32_t* b) {
    asm volatile(
        "mma.sync.aligned.m16n8k8.row.col.f32.tf32.tf32.f32 "
        "{%0,%1,%2,%3}, {%4,%5,%6,%7}, {%8,%9}, {%0,%1,%2,%3};\n"
        : "+f"(d[0]), "+f"(d[1]), "+f"(d[2]), "+f"(d[3])
        : "r"(a[0]), "r"(a[1]), "r"(a[2]), "r"(a[3]), "r"(b[0]), "r"(b[1]));
}

// ---------------- TF32 GEMM --------------------------------------------------
// C[M, ldc] (+bias, *alpha) = A[M,K] @ B   where B is:
//   BT=false: B[K,N] row-major (NN)     BT=true: B[N,K] row-major (C = A@B^T)
// Requirements: M%128==0, N%128==0, K%16==0. Operands pre-rounded to tf32.
// Store guard: cols < Nstore. ROUND_OUT: round C to tf32 on store.
#define ASTRIDE 20
#define BSTRIDE_NN 136

template<bool BT, bool ROUND_OUT>
__global__ __launch_bounds__(256, 2) void gemm_tf32(
    const float* __restrict__ A, const float* __restrict__ B,
    const float* __restrict__ bias, float* __restrict__ C,
    int M, int N, int K, int ldc, int Nstore, float alpha)
{
    __shared__ __align__(16) float As[2][128 * ASTRIDE];
    __shared__ __align__(16) float Bs[2][128 * ASTRIDE];  // NN uses 16*136=2176 <= 2560

    const int tid  = threadIdx.x;
    const int lane = tid & 31;
    const int wid  = tid >> 5;
    const int wm   = wid >> 2;          // 0..1  -> row offset wm*64
    const int wn   = wid & 3;           // 0..3  -> col offset wn*32
    const int row0 = blockIdx.y * 128;
    const int col0 = blockIdx.x * 128;

    // stage-load mappings
    const int am  = tid >> 2;           // 0..63 (+64 second iter)
    const int akc = (tid & 3) * 4;      // k-chunk offset in floats
    const int bk  = tid >> 5;           // NN: 0..7 (+8 second iter)
    const int bnc = (tid & 31) * 4;     // NN: col chunk

    const uint32_t sA = (uint32_t)__cvta_generic_to_shared(&As[0][0]);
    const uint32_t sB = (uint32_t)__cvta_generic_to_shared(&Bs[0][0]);
    const uint32_t bufBytes = 128 * ASTRIDE * 4;

    float acc[4][4][4];
#pragma unroll
    for (int i = 0; i < 4; i++)
#pragma unroll
        for (int j = 0; j < 4; j++)
#pragma unroll
            for (int t = 0; t < 4; t++) acc[i][j][t] = 0.f;

    const int stages = K >> 4;

    auto load_stage = [&](int s, int buf) {
        const int k0 = s << 4;
        uint32_t a0 = sA + buf * bufBytes;
        uint32_t b0 = sB + buf * bufBytes;
        // A: 128 rows x 16 k
#pragma unroll
        for (int it = 0; it < 2; it++) {
            int m = am + it * 64;
            cp16(a0 + (m * ASTRIDE + akc) * 4,
                 A + (size_t)(row0 + m) * K + k0 + akc);
        }
        if (BT) {
            // B^T: rows are C-cols: 128 n x 16 k, layout Bs[n][k] stride 20
#pragma unroll
            for (int it = 0; it < 2; it++) {
                int n = am + it * 64;
                cp16(b0 + (n * ASTRIDE + akc) * 4,
                     B + (size_t)(col0 + n) * K + k0 + akc);
            }
        } else {
            // B: 16 k x 128 n, layout Bs[k][n] stride 136
#pragma unroll
            for (int it = 0; it < 2; it++) {
                int k = bk + it * 8;
                cp16(b0 + (k * BSTRIDE_NN + bnc) * 4,
                     B + (size_t)(k0 + k) * N + col0 + bnc);
            }
        }
        cp_commit();
    };

    load_stage(0, 0);

    for (int s = 0; s < stages; s++) {
        cp_wait0();
        __syncthreads();
        if (s + 1 < stages) load_stage(s + 1, (s + 1) & 1);

        const float* Ab = As[s & 1];
        const float* Bb = Bs[s & 1];

#pragma unroll
        for (int kk = 0; kk < 16; kk += 8) {
            const int kb = kk + (lane & 3);
            uint32_t af[4][4];
#pragma unroll
            for (int tm = 0; tm < 4; tm++) {
                int r = wm * 64 + tm * 16 + (lane >> 2);
                af[tm][0] = __float_as_uint(Ab[r * ASTRIDE + kb]);
                af[tm][1] = __float_as_uint(Ab[(r + 8) * ASTRIDE + kb]);
                af[tm][2] = __float_as_uint(Ab[r * ASTRIDE + kb + 4]);
                af[tm][3] = __float_as_uint(Ab[(r + 8) * ASTRIDE + kb + 4]);
            }
            uint32_t bf[4][2];
#pragma unroll
            for (int tn = 0; tn < 4; tn++) {
                int c = wn * 32 + tn * 8 + (lane >> 2);
                if (BT) {
                    bf[tn][0] = __float_as_uint(Bb[c * ASTRIDE + kb]);
                    bf[tn][1] = __float_as_uint(Bb[c * ASTRIDE + kb + 4]);
                } else {
                    bf[tn][0] = __float_as_uint(Bb[kb * BSTRIDE_NN + c]);
                    bf[tn][1] = __float_as_uint(Bb[(kb + 4) * BSTRIDE_NN + c]);
                }
            }
#pragma unroll
            for (int tm = 0; tm < 4; tm++)
#pragma unroll
                for (int tn = 0; tn < 4; tn++)
                    mma_tf32(acc[tm][tn], af[tm], bf[tn]);
        }
        __syncthreads();
    }

    // epilogue
#pragma unroll
    for (int tm = 0; tm < 4; tm++) {
#pragma unroll
        for (int tn = 0; tn < 4; tn++) {
            int r = row0 + wm * 64 + tm * 16 + (lane >> 2);
            int c = col0 + wn * 32 + tn * 8 + 2 * (lane & 3);
#pragma unroll
            for (int half = 0; half < 2; half++) {
                int rr = r + half * 8;
                float v0 = alpha * acc[tm][tn][half * 2 + 0];
                float v1 = alpha * acc[tm][tn][half * 2 + 1];
                if (c + 1 < Nstore || c + 1 < N) {} // keep compiler honest
                if (c < Nstore) {
                    if (bias) { v0 += bias[c]; v1 += bias[c + 1]; }
                    if (ROUND_OUT) { v0 = rna_tf32(v0); v1 = rna_tf32(v1); }
                    float2 st = {v0, v1};
                    *(float2*)(C + (size_t)rr * ldc + c) = st;
                }
            }
        }
    }
}

// ---------------- rounding prep kernels -------------------------------------
__global__ void round_copy(const float* __restrict__ s, float* __restrict__ d, int n)
{
    int i = (blockIdx.x * 256 + threadIdx.x) * 4;
    if (i < n) {
        float4 v = *(const float4*)(s + i);
        v.x = rna_tf32(v.x); v.y = rna_tf32(v.y);
        v.z = rna_tf32(v.z); v.w = rna_tf32(v.w);
        *(float4*)(d + i) = v;
    }
}
__global__ void pad_round_fc(const float* __restrict__ s, float* __restrict__ d)
{
    int idx = blockIdx.x * 256 + threadIdx.x;   // DDIM*CPAD total
    int r = idx >> 10, c = idx & 1023;
    d[idx] = (c < CDIM) ? rna_tf32(s[r * CDIM + c]) : 0.f;
}

// ---------------- row softmax (in place) + tf32 rounding of probs ----------
__global__ __launch_bounds__(256) void softmax_rows(float* __restrict__ S, int n)
{
    __shared__ float red[256];
    const int row = blockIdx.x;
    const int tid = threadIdx.x;
    float* p = S + (size_t)row * n;

    float m = -3.4e38f;
    for (int i = tid * 4; i < n; i += 1024) {
        float4 v = *(const float4*)&p[i];
        m = fmaxf(m, fmaxf(fmaxf(v.x, v.y), fmaxf(v.z, v.w)));
    }
    red[tid] = m; __syncthreads();
    for (int s = 128; s > 0; s >>= 1) {
        if (tid < s) red[tid] = fmaxf(red[tid], red[tid + s]);
        __syncthreads();
    }
    m = red[0]; __syncthreads();

    float sum = 0.f;
    for (int i = tid * 4; i < n; i += 1024) {
        float4 v = *(float4*)&p[i];
        v.x = __expf(v.x - m); v.y = __expf(v.y - m);
        v.z = __expf(v.z - m); v.w = __expf(v.w - m);
        *(float4*)&p[i] = v;
        sum += v.x + v.y + v.z + v.w;
    }
    red[tid] = sum; __syncthreads();
    for (int s = 128; s > 0; s >>= 1) {
        if (tid < s) red[tid] += red[tid + s];
        __syncthreads();
    }
    float inv = 1.f / red[0];

    for (int i = tid * 4; i < n; i += 1024) {
        float4 v = *(float4*)&p[i];
        v.x = rna_tf32(v.x * inv); v.y = rna_tf32(v.y * inv);
        v.z = rna_tf32(v.z * inv); v.w = rna_tf32(v.w * inv);
        *(float4*)&p[i] = v;
    }
}

// ---------------- beta prep: fold concat-GEMV into two D-vectors ------------
__global__ void prep_beta(const float* __restrict__ Wb)
{
    int i = blockIdx.x * 256 + threadIdx.x;
    if (i < DDIM) {
        g_u[i] = Wb[i] + Wb[2 * DDIM + i];
        g_w[i] = Wb[DDIM + i] - Wb[2 * DDIM + i];
    }
}

// ---------------- fused beta + gate: h = beta*x_r + (1-beta)*a (tf32 out) ---
__global__ __launch_bounds__(256) void beta_gate(
    const float* __restrict__ a, const float* __restrict__ xr,
    const float* __restrict__ b_beta, float* __restrict__ h)
{
    __shared__ float sa[DDIM];
    __shared__ float sx[DDIM];
    __shared__ float red[256];
    const int row = blockIdx.x;
    const int tid = threadIdx.x;
    const float* pa = a  + (size_t)row * DDIM;
    const float* px = xr + (size_t)row * DDIM;

    float part = 0.f;
    for (int i = tid; i < DDIM; i += 256) {
        float av = pa[i], xv = px[i];
        sa[i] = av; sx[i] = xv;
        part += av * g_u[i] + xv * g_w[i];
    }
    red[tid] = part; __syncthreads();
    for (int s = 128; s > 0; s >>= 1) {
        if (tid < s) red[tid] += red[tid + s];
        __syncthreads();
    }
    float z = red[0] + b_beta[0];
    float beta = 1.f / (1.f + __expf(-z));

    float* ph = h + (size_t)row * DDIM;
    for (int i = tid; i < DDIM; i += 256)
        ph[i] = rna_tf32(beta * sx[i] + (1.f - beta) * sa[i]);
}

// ---------------------------------------------------------------------------
extern "C" void kernel_launch(void* const* d_in, const int* in_sizes, int n_in,
                              void* d_out, int out_size)
{
    const float* x      = (const float*)d_in[0];
    const float* W_skip = (const float*)d_in[1];
    const float* b_skip = (const float*)d_in[2];
    const float* W_q    = (const float*)d_in[3];
    const float* b_q    = (const float*)d_in[4];
    const float* W_k    = (const float*)d_in[5];
    const float* b_k    = (const float*)d_in[6];
    const float* W_v    = (const float*)d_in[7];
    const float* b_v    = (const float*)d_in[8];
    const float* W_beta = (const float*)d_in[9];
    const float* b_beta = (const float*)d_in[10];
    const float* W_fc   = (const float*)d_in[11];
    const float* b_fc   = (const float*)d_in[12];
    float* out = (float*)d_out;

    float *xr, *q, *k, *v, *a, *h, *s, *rx, *rws, *rwq, *rwk, *rwv, *rwf;
    cudaGetSymbolAddress((void**)&xr,  g_xr);
    cudaGetSymbolAddress((void**)&q,   g_q);
    cudaGetSymbolAddress((void**)&k,   g_k);
    cudaGetSymbolAddress((void**)&v,   g_v);
    cudaGetSymbolAddress((void**)&a,   g_a);
    cudaGetSymbolAddress((void**)&h,   g_h);
    cudaGetSymbolAddress((void**)&s,   g_s);
    cudaGetSymbolAddress((void**)&rx,  g_rx);
    cudaGetSymbolAddress((void**)&rws, g_rws);
    cudaGetSymbolAddress((void**)&rwq, g_rwq);
    cudaGetSymbolAddress((void**)&rwk, g_rwk);
    cudaGetSymbolAddress((void**)&rwv, g_rwv);
    cudaGetSymbolAddress((void**)&rwf, g_rwf);

    const int nd = NROWS * DDIM, dd = DDIM * DDIM;

    // pre-round operands to tf32 (RNA) so HMMA truncation is exact
    round_copy<<<(nd / 4 + 255) / 256, 256>>>(x, rx, nd);
    round_copy<<<(dd / 4 + 255) / 256, 256>>>(W_skip, rws, dd);
    round_copy<<<(dd / 4 + 255) / 256, 256>>>(W_q, rwq, dd);
    round_copy<<<(dd / 4 + 255) / 256, 256>>>(W_k, rwk, dd);
    round_copy<<<(dd / 4 + 255) / 256, 256>>>(W_v, rwv, dd);
    pad_round_fc<<<(DDIM * CPAD) / 256, 256>>>(W_fc, rwf);
    prep_beta<<<(DDIM + 255) / 256, 256>>>(W_beta);

    dim3 blk(256);
    dim3 gp(DDIM / 128, NROWS / 128);

    // projections (q,k,v outputs rounded for the next tf32 GEMMs)
    gemm_tf32<false, false><<<gp, blk>>>(rx, rws, b_skip, xr, NROWS, DDIM, DDIM, DDIM, DDIM, 1.f);
    gemm_tf32<false, true ><<<gp, blk>>>(rx, rwq, b_q,    q,  NROWS, DDIM, DDIM, DDIM, DDIM, 1.f);
    gemm_tf32<false, true ><<<gp, blk>>>(rx, rwk, b_k,    k,  NROWS, DDIM, DDIM, DDIM, DDIM, 1.f);
    gemm_tf32<false, true ><<<gp, blk>>>(rx, rwv, b_v,    v,  NROWS, DDIM, DDIM, DDIM, DDIM, 1.f);

    // scores = q @ k^T / 32
    dim3 gs(NROWS / 128, NROWS / 128);
    gemm_tf32<true, false><<<gs, blk>>>(q, k, (const float*)nullptr, s,
                                        NROWS, NROWS, DDIM, NROWS, NROWS, 0.03125f);

    // softmax rows (writes tf32-rounded probs)
    softmax_rows<<<NROWS, 256>>>(s, NROWS);

    // a = attn @ v
    gemm_tf32<false, false><<<gp, blk>>>(s, v, (const float*)nullptr, a,
                                         NROWS, DDIM, NROWS, DDIM, DDIM, 1.f);

    // h = beta*x_r + (1-beta)*a  (tf32-rounded)
    beta_gate<<<NROWS, 256>>>(a, xr, b_beta, h);

    // out = h @ W_fc + b_fc   (B padded to 1024 cols, store-guarded to 1000)
    dim3 gf(CPAD / 128, NROWS / 128);
    gemm_tf32<false, false><<<gf, blk>>>(h, rwf, b_fc, out,
                                         NROWS, CPAD, DDIM, CDIM, CDIM, 1.f);
}

// round 7
// speedup vs baseline: 9.0318x; 3.1350x over previous
#include <cuda_runtime.h>
#include <cstdint>
#include <cstddef>

#define NROWS 8192
#define DDIM  1024
#define CDIM  1000
#define CPAD  1024

// tcgen05 availability (evaluated per device-compilation pass)
#if defined(__CUDA_ARCH_FEAT_SM103_ALL) || defined(__CUDA_ARCH_FEAT_SM100_ALL) || defined(__CUDA_ARCH_FEAT_SM101_ALL)
#define HAS_TCGEN05 1
#else
#define HAS_TCGEN05 0
#endif

// tcgen05 GEMM tiling
#define BM   128
#define BN   256
#define BKF  32                         // K floats per stage = 128 B (SW128 row)
#define NST  4
#define STAGE_A_BYTES (BM * 128)        // 16384
#define STAGE_B_BYTES (BN * 128)        // 32768
#define STAGE_BYTES   (STAGE_A_BYTES + STAGE_B_BYTES)   // 49152
#define SMEM_DYN      (NST * STAGE_BYTES + 1024)

// ---------------- scratch (static device globals; no allocations) ----------
__device__ int   g_isa;                          // 1 = tcgen05 path compiled in
__device__ float g_xr [(size_t)NROWS * DDIM];
__device__ float g_q  [(size_t)NROWS * DDIM];
__device__ float g_k  [(size_t)NROWS * DDIM];
__device__ float g_v  [(size_t)NROWS * DDIM];
__device__ float g_vt [(size_t)DDIM * NROWS];
__device__ float g_a  [(size_t)NROWS * DDIM];
__device__ float g_h  [(size_t)NROWS * DDIM];
__device__ float g_s  [(size_t)NROWS * NROWS];   // 268 MB scores/attn
__device__ float g_rx [(size_t)NROWS * DDIM];
__device__ float g_wsT[(size_t)DDIM * DDIM];
__device__ float g_wqT[(size_t)DDIM * DDIM];
__device__ float g_wkT[(size_t)DDIM * DDIM];
__device__ float g_wvT[(size_t)DDIM * DDIM];
__device__ float g_wfT[(size_t)CPAD * DDIM];
__device__ float g_u  [DDIM];
__device__ float g_w  [DDIM];

// ---------------- generic helpers -------------------------------------------
__device__ __forceinline__ float rna_tf32(float x) {
    uint32_t u;
    asm("cvt.rna.tf32.f32 %0, %1;" : "=r"(u) : "f"(x));
    return __uint_as_float(u);
}
__device__ __forceinline__ void cp16(uint32_t s, const void* g) {
    asm volatile("cp.async.cg.shared.global [%0], [%1], 16;\n" :: "r"(s), "l"(g));
}
__device__ __forceinline__ void cp_commit() { asm volatile("cp.async.commit_group;\n"); }
template<int Ng> __device__ __forceinline__ void cp_waitg() {
    asm volatile("cp.async.wait_group %0;\n" :: "n"(Ng));
}
__device__ __forceinline__ uint32_t sw128(uint32_t off) { return off ^ ((off >> 3) & 0x70); }
__device__ __forceinline__ uint32_t s2u(const void* p) {
    return (uint32_t)__cvta_generic_to_shared(p);
}

// ---------------- tcgen05-only helpers (bodies guarded) ----------------------
__device__ __forceinline__ bool elect1() {
#if HAS_TCGEN05
    uint32_t p;
    asm volatile("{\n\t.reg .pred P;\n\telect.sync _|P, 0xFFFFFFFF;\n\t"
                 "selp.b32 %0, 1, 0, P;\n\t}" : "=r"(p));
    return p != 0;
#else
    return false;
#endif
}
__device__ __forceinline__ void mbar_init(uint32_t a, uint32_t c) {
    asm volatile("mbarrier.init.shared.b64 [%0], %1;" :: "r"(a), "r"(c) : "memory");
}
__device__ __forceinline__ void mbar_wait(uint32_t a, uint32_t parity) {
    asm volatile(
        "{\n\t.reg .pred P;\n\t"
        "W_%=:\n\t"
        "mbarrier.try_wait.parity.acquire.cta.shared::cta.b64 P, [%0], %1, 0x989680;\n\t"
        "@P bra.uni D_%=;\n\t"
        "bra.uni W_%=;\n\t"
        "D_%=:\n\t}"
        :: "r"(a), "r"(parity) : "memory");
}
// 64-bit SW128 K-major smem descriptor (LBO=1 -> 16B, SBO=64 -> 1024B atom)
__device__ __forceinline__ uint64_t sdesc(uint32_t addr) {
    return ((uint64_t)2 << 61) | ((uint64_t)1 << 46) | ((uint64_t)64 << 32)
         | ((uint64_t)1 << 16) | ((addr >> 4) & 0x3FFF);
}
__device__ __forceinline__ void mma_tf32_ss(uint32_t d, uint64_t ad, uint64_t bd,
                                            uint32_t idesc, uint32_t en) {
#if HAS_TCGEN05
    asm volatile(
        "{\n\t.reg .pred p;\n\tsetp.ne.u32 p, %4, 0;\n\t"
        "tcgen05.mma.cta_group::1.kind::tf32 [%0], %1, %2, %3, {%5,%5,%5,%5}, p;\n\t}"
        :: "r"(d), "l"(ad), "l"(bd), "r"(idesc), "r"(en), "r"(0u) : "memory");
#endif
}
__device__ __forceinline__ void t5_commit(uint32_t mbar) {
#if HAS_TCGEN05
    asm volatile(
        "tcgen05.commit.cta_group::1.mbarrier::arrive::one.shared::cluster.b64 [%0];"
        :: "r"(mbar) : "memory");
#endif
}
__device__ __forceinline__ void ldtm32(uint32_t* r, uint32_t addr) {
#if HAS_TCGEN05
    asm volatile(
        "tcgen05.ld.sync.aligned.32x32b.x32.b32 "
        "{%0,%1,%2,%3,%4,%5,%6,%7,%8,%9,%10,%11,%12,%13,%14,%15,"
        "%16,%17,%18,%19,%20,%21,%22,%23,%24,%25,%26,%27,%28,%29,%30,%31}, [%32];"
        : "=r"(r[0]),  "=r"(r[1]),  "=r"(r[2]),  "=r"(r[3]),
          "=r"(r[4]),  "=r"(r[5]),  "=r"(r[6]),  "=r"(r[7]),
          "=r"(r[8]),  "=r"(r[9]),  "=r"(r[10]), "=r"(r[11]),
          "=r"(r[12]), "=r"(r[13]), "=r"(r[14]), "=r"(r[15]),
          "=r"(r[16]), "=r"(r[17]), "=r"(r[18]), "=r"(r[19]),
          "=r"(r[20]), "=r"(r[21]), "=r"(r[22]), "=r"(r[23]),
          "=r"(r[24]), "=r"(r[25]), "=r"(r[26]), "=r"(r[27]),
          "=r"(r[28]), "=r"(r[29]), "=r"(r[30]), "=r"(r[31])
        : "r"(addr));
#endif
}

// ---------------- ISA detect -------------------------------------------------
__global__ void detect_isa() { g_isa = HAS_TCGEN05; }

// ---------------- tcgen05 TF32 GEMM (NT): C = alpha*(A[M,K] @ B[N,K]^T)+bias -
// M%128==0, N%256==0, K%32==0. Operands pre-rounded to tf32.
// Compiles to a no-op on targets without tcgen05.
template<bool ROUND_OUT>
__global__ __launch_bounds__(256, 1) __cluster_dims__(1, 1, 1)
void gemm_t5(const float* __restrict__ A, const float* __restrict__ B,
             const float* __restrict__ bias, float* __restrict__ C,
             int M, int N, int K, int ldc, int Nstore, float alpha)
{
#if HAS_TCGEN05
    extern __shared__ char dsm[];
    __shared__ uint32_t s_tmem;
    __shared__ __align__(8) uint64_t s_mbar[NST];

    const int tid  = threadIdx.x;
    const int lane = tid & 31;
    const int wid  = tid >> 5;
    const int row0 = blockIdx.y * BM;
    const int col0 = blockIdx.x * BN;

    const uint32_t base = (s2u(dsm) + 1023u) & ~1023u;

    if (tid == 0) {
#pragma unroll
        for (int i = 0; i < NST; i++) mbar_init(s2u(&s_mbar[i]), 1);
    }
    if (wid == 0) {
        asm volatile("tcgen05.alloc.cta_group::1.sync.aligned.shared::cta.b32 [%0], %1;"
                     :: "r"(s2u(&s_tmem)), "r"(256u) : "memory");
    }
    __syncthreads();
    const uint32_t tmem = s_tmem;

    const uint32_t idesc = (1u << 4) | (2u << 7) | (2u << 10)
                         | ((BN / 8) << 17) | ((BM / 16) << 24);

    const int stages = K / BKF;

    auto load_stage = [&](int s) {
        const int buf = s & (NST - 1);
        const int k0  = s * BKF;
        const uint32_t ab = base + buf * STAGE_BYTES;
        const uint32_t bb = ab + STAGE_A_BYTES;
#pragma unroll
        for (int it = 0; it < 4; it++) {
            int idx = tid + it * 256;
            int r = idx >> 3, cb = idx & 7;
            cp16(ab + sw128(r * 128 + cb * 16),
                 A + (size_t)(row0 + r) * K + k0 + cb * 4);
        }
#pragma unroll
        for (int it = 0; it < 8; it++) {
            int idx = tid + it * 256;
            int r = idx >> 3, cb = idx & 7;
            cp16(bb + sw128(r * 128 + cb * 16),
                 B + (size_t)(col0 + r) * K + k0 + cb * 4);
        }
        cp_commit();
    };

    const int pro = (stages < NST - 1) ? stages : NST - 1;
    for (int p = 0; p < pro; p++) load_stage(p);

    for (int s = 0; s < stages; s++) {
        const int rem = stages - 1 - s;
        if (rem >= NST - 2) cp_waitg<NST - 2>();
        else if (rem == 1)  cp_waitg<1>();
        else                cp_waitg<0>();
        __syncthreads();

        if (wid == 0) {
            asm volatile("fence.proxy.async.shared::cta;" ::: "memory");
            if (elect1()) {
                const uint32_t ab = base + (s & (NST - 1)) * STAGE_BYTES;
                const uint64_t ad = sdesc(ab);
                const uint64_t bd = sdesc(ab + STAGE_A_BYTES);
#pragma unroll
                for (int ks = 0; ks < 4; ks++)
                    mma_tf32_ss(tmem, ad + 2 * ks, bd + 2 * ks, idesc,
                                (s > 0 || ks > 0) ? 1u : 0u);
                t5_commit(s2u(&s_mbar[s & (NST - 1)]));
            }
        }

        const int t = s + NST - 1;
        if (t < stages) {
            if (s >= 1) mbar_wait(s2u(&s_mbar[(s - 1) & (NST - 1)]),
                                  (uint32_t)(((s - 1) / NST) & 1));
            load_stage(t);
        }
    }

    mbar_wait(s2u(&s_mbar[(stages - 1) & (NST - 1)]),
              (uint32_t)(((stages - 1) / NST) & 1));
    asm volatile("tcgen05.fence::after_thread_sync;" ::: "memory");

    // epilogue: warps 0-3 cols [0,128), warps 4-7 cols [128,256)
    {
        const int sub = wid & 3;
        const int colBase = (wid >> 2) * 128;
        const int r = row0 + sub * 32 + lane;
        uint32_t d[32];
#pragma unroll
        for (int cb = 0; cb < 4; cb++) {
            ldtm32(d, tmem + colBase + cb * 32);
            asm volatile("tcgen05.wait::ld.sync.aligned;" ::: "memory");
            const int c0 = col0 + colBase + cb * 32;
            float* cp = C + (size_t)r * ldc + c0;
            if (c0 + 31 < Nstore) {
#pragma unroll
                for (int j = 0; j < 32; j += 4) {
                    float4 v;
                    v.x = alpha * __uint_as_float(d[j + 0]);
                    v.y = alpha * __uint_as_float(d[j + 1]);
                    v.z = alpha * __uint_as_float(d[j + 2]);
                    v.w = alpha * __uint_as_float(d[j + 3]);
                    if (bias) {
                        v.x += bias[c0 + j + 0]; v.y += bias[c0 + j + 1];
                        v.z += bias[c0 + j + 2]; v.w += bias[c0 + j + 3];
                    }
                    if (ROUND_OUT) {
                        v.x = rna_tf32(v.x); v.y = rna_tf32(v.y);
                        v.z = rna_tf32(v.z); v.w = rna_tf32(v.w);
                    }
                    *(float4*)(cp + j) = v;
                }
            } else {
#pragma unroll
                for (int j = 0; j < 32; j++) {
                    if (c0 + j < Nstore) {
                        float v = alpha * __uint_as_float(d[j]);
                        if (bias) v += bias[c0 + j];
                        if (ROUND_OUT) v = rna_tf32(v);
                        cp[j] = v;
                    }
                }
            }
        }
        asm volatile("tcgen05.fence::before_thread_sync;" ::: "memory");
    }

    __syncthreads();
    if (wid == 0) {
        asm volatile("tcgen05.relinquish_alloc_permit.cta_group::1.sync.aligned;");
        asm volatile("tcgen05.dealloc.cta_group::1.sync.aligned.b32 %0, %1;"
                     :: "r"(tmem), "r"(256u));
    }
#endif  // HAS_TCGEN05
}

// ---------------- mma.sync TF32 fallback (NT): C = alpha*A@B^T + bias --------
// 128x128 tile, K%16==0. Early-exits if the tcgen05 path is active.
#define ASTRIDE 20
__device__ __forceinline__ void mma_tf32_frag(float* d, const uint32_t* a, const uint32_t* b) {
    asm volatile(
        "mma.sync.aligned.m16n8k8.row.col.f32.tf32.tf32.f32 "
        "{%0,%1,%2,%3}, {%4,%5,%6,%7}, {%8,%9}, {%0,%1,%2,%3};\n"
        : "+f"(d[0]), "+f"(d[1]), "+f"(d[2]), "+f"(d[3])
        : "r"(a[0]), "r"(a[1]), "r"(a[2]), "r"(a[3]), "r"(b[0]), "r"(b[1]));
}

template<bool ROUND_OUT>
__global__ __launch_bounds__(256, 2) void gemm_mma(
    const float* __restrict__ A, const float* __restrict__ B,
    const float* __restrict__ bias, float* __restrict__ C,
    int M, int N, int K, int ldc, int Nstore, float alpha)
{
    if (g_isa) return;   // tcgen05 kernel does the work

    __shared__ __align__(16) float As[2][128 * ASTRIDE];
    __shared__ __align__(16) float Bs[2][128 * ASTRIDE];

    const int tid  = threadIdx.x;
    const int lane = tid & 31;
    const int wid  = tid >> 5;
    const int wm   = wid >> 2;
    const int wn   = wid & 3;
    const int row0 = blockIdx.y * 128;
    const int col0 = blockIdx.x * 128;

    const int am  = tid >> 2;
    const int akc = (tid & 3) * 4;

    const uint32_t sA = s2u(&As[0][0]);
    const uint32_t sB = s2u(&Bs[0][0]);
    const uint32_t bufBytes = 128 * ASTRIDE * 4;

    float acc[4][4][4];
#pragma unroll
    for (int i = 0; i < 4; i++)
#pragma unroll
        for (int j = 0; j < 4; j++)
#pragma unroll
            for (int t = 0; t < 4; t++) acc[i][j][t] = 0.f;

    const int stages = K >> 4;

    auto load_stage = [&](int s, int buf) {
        const int k0 = s << 4;
        uint32_t a0 = sA + buf * bufBytes;
        uint32_t b0 = sB + buf * bufBytes;
#pragma unroll
        for (int it = 0; it < 2; it++) {
            int m = am + it * 64;
            cp16(a0 + (m * ASTRIDE + akc) * 4,
                 A + (size_t)(row0 + m) * K + k0 + akc);
            cp16(b0 + (m * ASTRIDE + akc) * 4,
                 B + (size_t)(col0 + m) * K + k0 + akc);
        }
        cp_commit();
    };

    load_stage(0, 0);

    for (int s = 0; s < stages; s++) {
        cp_waitg<0>();
        __syncthreads();
        if (s + 1 < stages) load_stage(s + 1, (s + 1) & 1);

        const float* Ab = As[s & 1];
        const float* Bb = Bs[s & 1];

#pragma unroll
        for (int kk = 0; kk < 16; kk += 8) {
            const int kb = kk + (lane & 3);
            uint32_t af[4][4];
#pragma unroll
            for (int tm = 0; tm < 4; tm++) {
                int r = wm * 64 + tm * 16 + (lane >> 2);
                af[tm][0] = __float_as_uint(Ab[r * ASTRIDE + kb]);
                af[tm][1] = __float_as_uint(Ab[(r + 8) * ASTRIDE + kb]);
                af[tm][2] = __float_as_uint(Ab[r * ASTRIDE + kb + 4]);
                af[tm][3] = __float_as_uint(Ab[(r + 8) * ASTRIDE + kb + 4]);
            }
            uint32_t bf[4][2];
#pragma unroll
            for (int tn = 0; tn < 4; tn++) {
                int c = wn * 32 + tn * 8 + (lane >> 2);
                bf[tn][0] = __float_as_uint(Bb[c * ASTRIDE + kb]);
                bf[tn][1] = __float_as_uint(Bb[c * ASTRIDE + kb + 4]);
            }
#pragma unroll
            for (int tm = 0; tm < 4; tm++)
#pragma unroll
                for (int tn = 0; tn < 4; tn++)
                    mma_tf32_frag(acc[tm][tn], af[tm], bf[tn]);
        }
        __syncthreads();
    }

#pragma unroll
    for (int tm = 0; tm < 4; tm++) {
#pragma unroll
        for (int tn = 0; tn < 4; tn++) {
            int r = row0 + wm * 64 + tm * 16 + (lane >> 2);
            int c = col0 + wn * 32 + tn * 8 + 2 * (lane & 3);
#pragma unroll
            for (int half = 0; half < 2; half++) {
                int rr = r + half * 8;
                float v0 = alpha * acc[tm][tn][half * 2 + 0];
                float v1 = alpha * acc[tm][tn][half * 2 + 1];
                if (c < Nstore) {
                    if (bias) { v0 += bias[c]; v1 += bias[c + 1]; }
                    if (ROUND_OUT) { v0 = rna_tf32(v0); v1 = rna_tf32(v1); }
                    float2 st = {v0, v1};
                    *(float2*)(C + (size_t)rr * ldc + c) = st;
                }
            }
        }
    }
}

// ---------------- tiled transpose + tf32 round (+row pad with zeros) --------
__global__ __launch_bounds__(256) void transpose_rna(
    const float* __restrict__ in, float* __restrict__ out, int R, int C, int outR)
{
    __shared__ float t[32][33];
    const int bx = blockIdx.x * 32;
    const int by = blockIdx.y * 32;
    const int x = threadIdx.x & 31;
    const int y = threadIdx.x >> 5;
#pragma unroll
    for (int dy = 0; dy < 4; dy++) {
        int r = by + y + dy * 8, c = bx + x;
        t[y + dy * 8][x] = (c < C) ? in[(size_t)r * C + c] : 0.f;
    }
    __syncthreads();
#pragma unroll
    for (int dy = 0; dy < 4; dy++) {
        int c = bx + y + dy * 8, r = by + x;
        if (c < outR) out[(size_t)c * R + r] = rna_tf32(t[x][y + dy * 8]);
    }
}

// ---------------- elementwise prep ------------------------------------------
__global__ void round_copy(const float* __restrict__ s, float* __restrict__ d, int n)
{
    int i = (blockIdx.x * 256 + threadIdx.x) * 4;
    if (i < n) {
        float4 v = *(const float4*)(s + i);
        v.x = rna_tf32(v.x); v.y = rna_tf32(v.y);
        v.z = rna_tf32(v.z); v.w = rna_tf32(v.w);
        *(float4*)(d + i) = v;
    }
}
__global__ void prep_beta(const float* __restrict__ Wb)
{
    int i = blockIdx.x * 256 + threadIdx.x;
    if (i < DDIM) {
        g_u[i] = Wb[i] + Wb[2 * DDIM + i];
        g_w[i] = Wb[DDIM + i] - Wb[2 * DDIM + i];
    }
}

// ---------------- row softmax (in place) + tf32 rounding of probs -----------
__global__ __launch_bounds__(256) void softmax_rows(float* __restrict__ S, int n)
{
    __shared__ float red[256];
    const int row = blockIdx.x;
    const int tid = threadIdx.x;
    float* p = S + (size_t)row * n;

    float m = -3.4e38f;
    for (int i = tid * 4; i < n; i += 1024) {
        float4 v = *(const float4*)&p[i];
        m = fmaxf(m, fmaxf(fmaxf(v.x, v.y), fmaxf(v.z, v.w)));
    }
    red[tid] = m; __syncthreads();
    for (int s = 128; s > 0; s >>= 1) {
        if (tid < s) red[tid] = fmaxf(red[tid], red[tid + s]);
        __syncthreads();
    }
    m = red[0]; __syncthreads();

    float sum = 0.f;
    for (int i = tid * 4; i < n; i += 1024) {
        float4 v = *(float4*)&p[i];
        v.x = __expf(v.x - m); v.y = __expf(v.y - m);
        v.z = __expf(v.z - m); v.w = __expf(v.w - m);
        *(float4*)&p[i] = v;
        sum += v.x + v.y + v.z + v.w;
    }
    red[tid] = sum; __syncthreads();
    for (int s = 128; s > 0; s >>= 1) {
        if (tid < s) red[tid] += red[tid + s];
        __syncthreads();
    }
    float inv = 1.f / red[0];

    for (int i = tid * 4; i < n; i += 1024) {
        float4 v = *(float4*)&p[i];
        v.x = rna_tf32(v.x * inv); v.y = rna_tf32(v.y * inv);
        v.z = rna_tf32(v.z * inv); v.w = rna_tf32(v.w * inv);
        *(float4*)&p[i] = v;
    }
}

// ---------------- fused beta + gate: h = beta*x_r + (1-beta)*a (tf32 out) ---
__global__ __launch_bounds__(256) void beta_gate(
    const float* __restrict__ a, const float* __restrict__ xr,
    const float* __restrict__ b_beta, float* __restrict__ h)
{
    __shared__ float sa[DDIM];
    __shared__ float sx[DDIM];
    __shared__ float red[256];
    const int row = blockIdx.x;
    const int tid = threadIdx.x;
    const float* pa = a  + (size_t)row * DDIM;
    const float* px = xr + (size_t)row * DDIM;

    float part = 0.f;
    for (int i = tid; i < DDIM; i += 256) {
        float av = pa[i], xv = px[i];
        sa[i] = av; sx[i] = xv;
        part += av * g_u[i] + xv * g_w[i];
    }
    red[tid] = part; __syncthreads();
    for (int s = 128; s > 0; s >>= 1) {
        if (tid < s) red[tid] += red[tid + s];
        __syncthreads();
    }
    float z = red[0] + b_beta[0];
    float beta = 1.f / (1.f + __expf(-z));

    float* ph = h + (size_t)row * DDIM;
    for (int i = tid; i < DDIM; i += 256)
        ph[i] = rna_tf32(beta * sx[i] + (1.f - beta) * sa[i]);
}

// ---------------------------------------------------------------------------
static void launch_gemm(const float* A, const float* B, const float* bias,
                        float* C, int M, int N, int K, int ldc, int Nstore,
                        float alpha, bool round_out)
{
    dim3 g5(N / BN, M / BM);
    dim3 gm(N / 128, M / 128);
    if (round_out) {
        gemm_t5 <true><<<g5, 256, SMEM_DYN>>>(A, B, bias, C, M, N, K, ldc, Nstore, alpha);
        gemm_mma<true><<<gm, 256>>>(A, B, bias, C, M, N, K, ldc, Nstore, alpha);
    } else {
        gemm_t5 <false><<<g5, 256, SMEM_DYN>>>(A, B, bias, C, M, N, K, ldc, Nstore, alpha);
        gemm_mma<false><<<gm, 256>>>(A, B, bias, C, M, N, K, ldc, Nstore, alpha);
    }
}

extern "C" void kernel_launch(void* const* d_in, const int* in_sizes, int n_in,
                              void* d_out, int out_size)
{
    const float* x      = (const float*)d_in[0];
    const float* W_skip = (const float*)d_in[1];
    const float* b_skip = (const float*)d_in[2];
    const float* W_q    = (const float*)d_in[3];
    const float* b_q    = (const float*)d_in[4];
    const float* W_k    = (const float*)d_in[5];
    const float* b_k    = (const float*)d_in[6];
    const float* W_v    = (const float*)d_in[7];
    const float* b_v    = (const float*)d_in[8];
    const float* W_beta = (const float*)d_in[9];
    const float* b_beta = (const float*)d_in[10];
    const float* W_fc   = (const float*)d_in[11];
    const float* b_fc   = (const float*)d_in[12];
    float* out = (float*)d_out;

    float *xr, *q, *k, *v, *vt, *a, *h, *s, *rx, *wsT, *wqT, *wkT, *wvT, *wfT;
    cudaGetSymbolAddress((void**)&xr,  g_xr);
    cudaGetSymbolAddress((void**)&q,   g_q);
    cudaGetSymbolAddress((void**)&k,   g_k);
    cudaGetSymbolAddress((void**)&v,   g_v);
    cudaGetSymbolAddress((void**)&vt,  g_vt);
    cudaGetSymbolAddress((void**)&a,   g_a);
    cudaGetSymbolAddress((void**)&h,   g_h);
    cudaGetSymbolAddress((void**)&s,   g_s);
    cudaGetSymbolAddress((void**)&rx,  g_rx);
    cudaGetSymbolAddress((void**)&wsT, g_wsT);
    cudaGetSymbolAddress((void**)&wqT, g_wqT);
    cudaGetSymbolAddress((void**)&wkT, g_wkT);
    cudaGetSymbolAddress((void**)&wvT, g_wvT);
    cudaGetSymbolAddress((void**)&wfT, g_wfT);

    cudaFuncSetAttribute((const void*)gemm_t5<false>,
                         cudaFuncAttributeMaxDynamicSharedMemorySize, SMEM_DYN);
    cudaFuncSetAttribute((const void*)gemm_t5<true>,
                         cudaFuncAttributeMaxDynamicSharedMemorySize, SMEM_DYN);

    const int nd = NROWS * DDIM;

    detect_isa<<<1, 1>>>();

    // prep: round x; transpose+round weights (W_fc padded to 1024 rows)
    round_copy<<<(nd / 4 + 255) / 256, 256>>>(x, rx, nd);
    dim3 tb(256);
    dim3 tgW(32, 32);
    transpose_rna<<<tgW, tb>>>(W_skip, wsT, DDIM, DDIM, DDIM);
    transpose_rna<<<tgW, tb>>>(W_q,    wqT, DDIM, DDIM, DDIM);
    transpose_rna<<<tgW, tb>>>(W_k,    wkT, DDIM, DDIM, DDIM);
    transpose_rna<<<tgW, tb>>>(W_v,    wvT, DDIM, DDIM, DDIM);
    transpose_rna<<<tgW, tb>>>(W_fc,   wfT, DDIM, CDIM, CPAD);
    prep_beta<<<(DDIM + 255) / 256, 256>>>(W_beta);

    // projections: C = x @ W == x[M,K] @ (W^T)[N,K]^T
    launch_gemm(rx, wsT, b_skip, xr, NROWS, DDIM, DDIM, DDIM, DDIM, 1.f, false);
    launch_gemm(rx, wqT, b_q,    q,  NROWS, DDIM, DDIM, DDIM, DDIM, 1.f, true);
    launch_gemm(rx, wkT, b_k,    k,  NROWS, DDIM, DDIM, DDIM, DDIM, 1.f, true);
    launch_gemm(rx, wvT, b_v,    v,  NROWS, DDIM, DDIM, DDIM, DDIM, 1.f, false);

    // v^T for the AV GEMM (rounded during transpose)
    dim3 tgV(32, NROWS / 32);
    transpose_rna<<<tgV, tb>>>(v, vt, NROWS, DDIM, DDIM);

    // scores = q @ k^T / 32 (k already [N,K])
    launch_gemm(q, k, nullptr, s, NROWS, NROWS, DDIM, NROWS, NROWS, 0.03125f, false);

    // softmax rows (writes tf32-rounded probs)
    softmax_rows<<<NROWS, 256>>>(s, NROWS);

    // a = attn @ v == attn[M,K] @ vT[N,K]^T
    launch_gemm(s, vt, nullptr, a, NROWS, DDIM, NROWS, DDIM, DDIM, 1.f, false);

    // h = beta*x_r + (1-beta)*a (tf32-rounded)
    beta_gate<<<NROWS, 256>>>(a, xr, b_beta, h);

    // out = h @ W_fc + b_fc (wfT padded to 1024 rows; store-guarded to 1000)
    launch_gemm(h, wfT, b_fc, out, NROWS, CPAD, DDIM, CDIM, CDIM, 1.f, false);
}

// round 8
// speedup vs baseline: 9.4643x; 1.0479x over previous
#include <cuda_runtime.h>
#include <cstdint>
#include <cstddef>

#define NROWS 8192
#define DDIM  1024
#define CDIM  1000
#define NPROJ 4096   // skip|q|k|v packed

#if defined(__CUDA_ARCH_FEAT_SM103_ALL) || defined(__CUDA_ARCH_FEAT_SM100_ALL) || defined(__CUDA_ARCH_FEAT_SM101_ALL)
#define HAS_TCGEN05 1
#else
#define HAS_TCGEN05 0
#endif

// cg2 GEMM tiling: cluster tile 256x256, per CTA: A 128rows + B 128rows (N-split)
#define NST  4
#define C2_A_BYTES 16384
#define C2_B_BYTES 16384
#define C2_STAGE   (C2_A_BYTES + C2_B_BYTES)     // 32 KB
#define C2_SMEM    (NST * C2_STAGE + 1024)

// ---------------- scratch (static device globals; no allocations) ----------
__device__ float g_p  [(size_t)NROWS * NPROJ];   // packed skip|q|k|v  (134 MB)
__device__ float g_vt [(size_t)DDIM * NROWS];
__device__ float g_a  [(size_t)NROWS * DDIM];
__device__ float g_h  [(size_t)NROWS * DDIM];
__device__ float g_s  [(size_t)NROWS * NROWS];   // 268 MB scores / exp
__device__ float g_rx [(size_t)NROWS * DDIM];
__device__ float g_wcT[(size_t)NPROJ * DDIM];    // concat(Wskip,Wq,Wk,Wv)^T
__device__ float g_wfT[(size_t)DDIM * DDIM];     // W_fc^T padded to 1024 rows
__device__ float g_bc [NPROJ];                   // concat biases
__device__ float g_inv[NROWS];                   // 1/rowsum(exp)
__device__ float g_u  [DDIM];
__device__ float g_w  [DDIM];

// ---------------- generic helpers -------------------------------------------
__device__ __forceinline__ float rna_tf32(float x) {
    uint32_t u;
    asm("cvt.rna.tf32.f32 %0, %1;" : "=r"(u) : "f"(x));
    return __uint_as_float(u);
}
__device__ __forceinline__ void cp16(uint32_t s, const void* g) {
    asm volatile("cp.async.cg.shared.global [%0], [%1], 16;\n" :: "r"(s), "l"(g));
}
__device__ __forceinline__ void cp_commit() { asm volatile("cp.async.commit_group;\n"); }
template<int Ng> __device__ __forceinline__ void cp_waitg() {
    asm volatile("cp.async.wait_group %0;\n" :: "n"(Ng));
}
__device__ __forceinline__ uint32_t sw128(uint32_t off) { return off ^ ((off >> 3) & 0x70); }
__device__ __forceinline__ uint32_t s2u(const void* p) {
    return (uint32_t)__cvta_generic_to_shared(p);
}

// ---------------- tcgen05/cluster helpers (guarded) --------------------------
__device__ __forceinline__ bool elect1() {
#if HAS_TCGEN05
    uint32_t p;
    asm volatile("{\n\t.reg .pred P;\n\telect.sync _|P, 0xFFFFFFFF;\n\t"
                 "selp.b32 %0, 1, 0, P;\n\t}" : "=r"(p));
    return p != 0;
#else
    return false;
#endif
}
__device__ __forceinline__ void mbar_init(uint32_t a, uint32_t c) {
    asm volatile("mbarrier.init.shared.b64 [%0], %1;" :: "r"(a), "r"(c) : "memory");
}
__device__ __forceinline__ void mbar_wait(uint32_t a, uint32_t parity) {
    asm volatile(
        "{\n\t.reg .pred P;\n\t"
        "W_%=:\n\t"
        "mbarrier.try_wait.parity.acquire.cta.shared::cta.b64 P, [%0], %1, 0x989680;\n\t"
        "@P bra.uni D_%=;\n\t"
        "bra.uni W_%=;\n\t"
        "D_%=:\n\t}"
        :: "r"(a), "r"(parity) : "memory");
}
__device__ __forceinline__ void mbar_wait_cluster(uint32_t a, uint32_t parity) {
#if HAS_TCGEN05
    asm volatile(
        "{\n\t.reg .pred P;\n\t"
        "W_%=:\n\t"
        "mbarrier.try_wait.parity.acquire.cluster.shared::cta.b64 P, [%0], %1, 0x989680;\n\t"
        "@P bra.uni D_%=;\n\t"
        "bra.uni W_%=;\n\t"
        "D_%=:\n\t}"
        :: "r"(a), "r"(parity) : "memory");
#endif
}
__device__ __forceinline__ void arrive_rank0(uint32_t local_addr) {
#if HAS_TCGEN05
    asm volatile(
        "{\n\t.reg .b32 ra;\n\t"
        "mapa.shared::cluster.u32 ra, %0, 0;\n\t"
        "mbarrier.arrive.shared::cluster.b64 _, [ra];\n\t}"
        :: "r"(local_addr) : "memory");
#endif
}
__device__ __forceinline__ void cluster_sync() {
#if HAS_TCGEN05
    asm volatile("barrier.cluster.arrive.aligned;" ::: "memory");
    asm volatile("barrier.cluster.wait.aligned;" ::: "memory");
#endif
}
// 64-bit SW128 K-major smem descriptor
__device__ __forceinline__ uint64_t sdesc(uint32_t addr) {
    return ((uint64_t)2 << 61) | ((uint64_t)1 << 46) | ((uint64_t)64 << 32)
         | ((uint64_t)1 << 16) | ((addr >> 4) & 0x3FFF);
}
__device__ __forceinline__ void mma_tf32_cg2(uint32_t d, uint64_t ad, uint64_t bd,
                                             uint32_t idesc, uint32_t en) {
#if HAS_TCGEN05
    asm volatile(
        "{\n\t.reg .pred p;\n\tsetp.ne.u32 p, %4, 0;\n\t"
        "tcgen05.mma.cta_group::2.kind::tf32 [%0], %1, %2, %3, "
        "{%5,%5,%5,%5,%5,%5,%5,%5}, p;\n\t}"
        :: "r"(d), "l"(ad), "l"(bd), "r"(idesc), "r"(en), "r"(0u) : "memory");
#endif
}
__device__ __forceinline__ void commit_mc2(uint32_t mbar) {
#if HAS_TCGEN05
    asm volatile(
        "tcgen05.commit.cta_group::2.mbarrier::arrive::one.shared::cluster"
        ".multicast::cluster.b64 [%0], %1;"
        :: "r"(mbar), "h"((uint16_t)0x3) : "memory");
#endif
}
__device__ __forceinline__ void ldtm32(uint32_t* r, uint32_t addr) {
#if HAS_TCGEN05
    asm volatile(
        "tcgen05.ld.sync.aligned.32x32b.x32.b32 "
        "{%0,%1,%2,%3,%4,%5,%6,%7,%8,%9,%10,%11,%12,%13,%14,%15,"
        "%16,%17,%18,%19,%20,%21,%22,%23,%24,%25,%26,%27,%28,%29,%30,%31}, [%32];"
        : "=r"(r[0]),  "=r"(r[1]),  "=r"(r[2]),  "=r"(r[3]),
          "=r"(r[4]),  "=r"(r[5]),  "=r"(r[6]),  "=r"(r[7]),
          "=r"(r[8]),  "=r"(r[9]),  "=r"(r[10]), "=r"(r[11]),
          "=r"(r[12]), "=r"(r[13]), "=r"(r[14]), "=r"(r[15]),
          "=r"(r[16]), "=r"(r[17]), "=r"(r[18]), "=r"(r[19]),
          "=r"(r[20]), "=r"(r[21]), "=r"(r[22]), "=r"(r[23]),
          "=r"(r[24]), "=r"(r[25]), "=r"(r[26]), "=r"(r[27]),
          "=r"(r[28]), "=r"(r[29]), "=r"(r[30]), "=r"(r[31])
        : "r"(addr));
#endif
}

// ---------------- cg2 tcgen05 TF32 GEMM (NT) ---------------------------------
// Cluster pair computes C[256, 256] tile: C = alpha*(A[M,K] @ B[N,K]^T)(+bias)
// optionally * rowscale[r]. grid = (2*N/256, M/256), cluster (2,1,1).
// M%256==0, N%256==0, K%32==0. Operands tf32-rounded. Store cols < Nstore.
template<bool ROUND_OUT, bool ROWSCALE>
__global__ __launch_bounds__(256, 1) __cluster_dims__(2, 1, 1)
void gemm_cg2(const float* __restrict__ A, int lda,
              const float* __restrict__ B, int ldb,
              const float* __restrict__ bias, const float* __restrict__ rowscale,
              float* __restrict__ C, int ldc, int K, int Nstore, float alpha)
{
#if HAS_TCGEN05
    extern __shared__ char dsm[];
    __shared__ uint32_t s_tmem;
    __shared__ __align__(8) uint64_t s_full[NST];   // leader-consumed, count 2
    __shared__ __align__(8) uint64_t s_done[NST];   // per-CTA, multicast commit

    const int tid  = threadIdx.x;
    const int lane = tid & 31;
    const int wid  = tid >> 5;
    uint32_t rank;
    asm("mov.u32 %0, %%cluster_ctarank;" : "=r"(rank));

    const int col0  = (blockIdx.x >> 1) * 256;
    const int row0  = blockIdx.y * 256;
    const int aRow0 = row0 + (int)rank * 128;       // this CTA's 128 M-rows
    const int bRow0 = col0 + (int)rank * 128;       // this CTA's 128 B-rows (N-split)

    const uint32_t base = (s2u(dsm) + 1023u) & ~1023u;

    if (tid == 0) {
#pragma unroll
        for (int i = 0; i < NST; i++) {
            mbar_init(s2u(&s_full[i]), 2);
            mbar_init(s2u(&s_done[i]), 1);
        }
    }
    if (wid == 0) {
        asm volatile("tcgen05.alloc.cta_group::2.sync.aligned.shared::cta.b32 [%0], %1;"
                     :: "r"(s2u(&s_tmem)), "r"(256u) : "memory");
    }
    __syncthreads();
    cluster_sync();                                  // barriers visible cluster-wide
    const uint32_t tmem = s_tmem;

    // idesc: F32 acc, tf32 a/b, N=256, M=256 (cg2)
    const uint32_t idesc = (1u << 4) | (2u << 7) | (2u << 10)
                         | ((256 / 8) << 17) | ((256 / 16) << 24);

    const int stages = K / 32;

    auto load_stage = [&](int s) {
        const int buf = s & (NST - 1);
        const int k0  = s * 32;
        const uint32_t ab = base + buf * C2_STAGE;
        const uint32_t bb = ab + C2_A_BYTES;
#pragma unroll
        for (int it = 0; it < 4; it++) {
            int idx = tid + it * 256;
            int r = idx >> 3, cb = idx & 7;
            cp16(ab + sw128(r * 128 + cb * 16),
                 A + (size_t)(aRow0 + r) * lda + k0 + cb * 4);
        }
#pragma unroll
        for (int it = 0; it < 4; it++) {
            int idx = tid + it * 256;
            int r = idx >> 3, cb = idx & 7;
            cp16(bb + sw128(r * 128 + cb * 16),
                 B + (size_t)(bRow0 + r) * ldb + k0 + cb * 4);
        }
        cp_commit();
    };

    const int pro = (stages < NST - 1) ? stages : NST - 1;
    for (int p = 0; p < pro; p++) load_stage(p);

    for (int s = 0; s < stages; s++) {
        const int rem = stages - 1 - s;
        if (rem >= NST - 2) cp_waitg<NST - 2>();
        else if (rem == 1)  cp_waitg<1>();
        else                cp_waitg<0>();
        __syncthreads();                             // stage-s tile resident CTA-wide

        if (tid == 0) {
            asm volatile("fence.proxy.async.shared::cta;" ::: "memory");
            arrive_rank0(s2u(&s_full[s & (NST - 1)]));
        }

        if (rank == 0 && wid == 0) {
            if (elect1()) {
                mbar_wait_cluster(s2u(&s_full[s & (NST - 1)]),
                                  (uint32_t)((s / NST) & 1));
                const uint32_t ab = base + (s & (NST - 1)) * C2_STAGE;
                const uint64_t ad = sdesc(ab);
                const uint64_t bd = sdesc(ab + C2_A_BYTES);
#pragma unroll
                for (int ks = 0; ks < 4; ks++)
                    mma_tf32_cg2(tmem, ad + 2 * ks, bd + 2 * ks, idesc,
                                 (s > 0 || ks > 0) ? 1u : 0u);
                commit_mc2(s2u(&s_done[s & (NST - 1)]));
            }
        }

        const int t = s + NST - 1;
        if (t < stages) {
            if (s >= 1) mbar_wait(s2u(&s_done[(s - 1) & (NST - 1)]),
                                  (uint32_t)(((s - 1) / NST) & 1));
            load_stage(t);
        }
    }

    mbar_wait(s2u(&s_done[(stages - 1) & (NST - 1)]),
              (uint32_t)(((stages - 1) / NST) & 1));
    asm volatile("tcgen05.fence::after_thread_sync;" ::: "memory");

    // epilogue: this CTA's 128 rows x 256 cols live in its own TMEM
    {
        const int sub = wid & 3;
        const int colBase = (wid >> 2) * 128;
        const int r = aRow0 + sub * 32 + lane;
        float scale = alpha;
        if (ROWSCALE) scale *= rowscale[r];
        uint32_t d[32];
#pragma unroll
        for (int cb = 0; cb < 4; cb++) {
            ldtm32(d, tmem + colBase + cb * 32);
            asm volatile("tcgen05.wait::ld.sync.aligned;" ::: "memory");
            const int c0 = col0 + colBase + cb * 32;
            float* cp = C + (size_t)r * ldc + c0;
            if (c0 + 31 < Nstore) {
#pragma unroll
                for (int j = 0; j < 32; j += 4) {
                    float4 v;
                    v.x = scale * __uint_as_float(d[j + 0]);
                    v.y = scale * __uint_as_float(d[j + 1]);
                    v.z = scale * __uint_as_float(d[j + 2]);
                    v.w = scale * __uint_as_float(d[j + 3]);
                    if (bias) {
                        v.x += bias[c0 + j + 0]; v.y += bias[c0 + j + 1];
                        v.z += bias[c0 + j + 2]; v.w += bias[c0 + j + 3];
                    }
                    if (ROUND_OUT) {
                        v.x = rna_tf32(v.x); v.y = rna_tf32(v.y);
                        v.z = rna_tf32(v.z); v.w = rna_tf32(v.w);
                    }
                    *(float4*)(cp + j) = v;
                }
            } else {
#pragma unroll
                for (int j = 0; j < 32; j++) {
                    if (c0 + j < Nstore) {
                        float v = scale * __uint_as_float(d[j]);
                        if (bias) v += bias[c0 + j];
                        if (ROUND_OUT) v = rna_tf32(v);
                        cp[j] = v;
                    }
                }
            }
        }
        asm volatile("tcgen05.fence::before_thread_sync;" ::: "memory");
    }

    __syncthreads();
    if (wid == 0) {
        asm volatile("tcgen05.relinquish_alloc_permit.cta_group::2.sync.aligned;");
        asm volatile("tcgen05.dealloc.cta_group::2.sync.aligned.b32 %0, %1;"
                     :: "r"(tmem), "r"(256u));
    }
    cluster_sync();
#endif  // HAS_TCGEN05
}

// ---------------- tiled transpose + tf32 round (+row pad with zeros) --------
// out[c][r] = rna(in[r*in_ld + c]) for c < outR else skipped; out ld = R.
__global__ __launch_bounds__(256) void transpose_rna(
    const float* __restrict__ in, int in_ld, float* __restrict__ out,
    int R, int C, int outR)
{
    __shared__ float t[32][33];
    const int bx = blockIdx.x * 32;   // c block
    const int by = blockIdx.y * 32;   // r block
    const int x = threadIdx.x & 31;
    const int y = threadIdx.x >> 5;
#pragma unroll
    for (int dy = 0; dy < 4; dy++) {
        int r = by + y + dy * 8, c = bx + x;
        t[y + dy * 8][x] = (c < C) ? in[(size_t)r * in_ld + c] : 0.f;
    }
    __syncthreads();
#pragma unroll
    for (int dy = 0; dy < 4; dy++) {
        int c = bx + y + dy * 8, r = by + x;
        if (c < outR) out[(size_t)c * R + r] = rna_tf32(t[x][y + dy * 8]);
    }
}

// ---------------- elementwise prep ------------------------------------------
__global__ void round_copy(const float* __restrict__ s, float* __restrict__ d, int n)
{
    int i = (blockIdx.x * 256 + threadIdx.x) * 4;
    if (i < n) {
        float4 v = *(const float4*)(s + i);
        v.x = rna_tf32(v.x); v.y = rna_tf32(v.y);
        v.z = rna_tf32(v.z); v.w = rna_tf32(v.w);
        *(float4*)(d + i) = v;
    }
}
__global__ void concat_bias(const float* __restrict__ bs, const float* __restrict__ bq,
                            const float* __restrict__ bk, const float* __restrict__ bv)
{
    int i = blockIdx.x * 256 + threadIdx.x;
    if (i < NPROJ) {
        int sec = i >> 10, c = i & 1023;
        g_bc[i] = (sec == 0) ? bs[c] : (sec == 1) ? bq[c] : (sec == 2) ? bk[c] : bv[c];
    }
}
__global__ void prep_beta(const float* __restrict__ Wb)
{
    int i = blockIdx.x * 256 + threadIdx.x;
    if (i < DDIM) {
        g_u[i] = Wb[i] + Wb[2 * DDIM + i];
        g_w[i] = Wb[DDIM + i] - Wb[2 * DDIM + i];
    }
}

// ---------------- single-pass exp (no max-shift; scores are O(1)) -----------
// S <- rna_tf32(exp(S)); g_inv[row] = 1/rowsum.
__global__ __launch_bounds__(256) void exp_rows(float* __restrict__ S, int n)
{
    __shared__ float red[256];
    const int row = blockIdx.x;
    const int tid = threadIdx.x;
    float* p = S + (size_t)row * n;

    float sum = 0.f;
    for (int i = tid * 4; i < n; i += 1024) {
        float4 v = *(float4*)&p[i];
        v.x = rna_tf32(__expf(v.x)); v.y = rna_tf32(__expf(v.y));
        v.z = rna_tf32(__expf(v.z)); v.w = rna_tf32(__expf(v.w));
        *(float4*)&p[i] = v;
        sum += v.x + v.y + v.z + v.w;
    }
    red[tid] = sum; __syncthreads();
    for (int s = 128; s > 0; s >>= 1) {
        if (tid < s) red[tid] += red[tid + s];
        __syncthreads();
    }
    if (tid == 0) g_inv[row] = 1.f / red[0];
}

// ---------------- fused beta + gate: h = beta*x_r + (1-beta)*a (tf32 out) ---
__global__ __launch_bounds__(256) void beta_gate(
    const float* __restrict__ a, const float* __restrict__ xr, int xld,
    const float* __restrict__ b_beta, float* __restrict__ h)
{
    __shared__ float sa[DDIM];
    __shared__ float sx[DDIM];
    __shared__ float red[256];
    const int row = blockIdx.x;
    const int tid = threadIdx.x;
    const float* pa = a  + (size_t)row * DDIM;
    const float* px = xr + (size_t)row * xld;

    float part = 0.f;
    for (int i = tid; i < DDIM; i += 256) {
        float av = pa[i], xv = px[i];
        sa[i] = av; sx[i] = xv;
        part += av * g_u[i] + xv * g_w[i];
    }
    red[tid] = part; __syncthreads();
    for (int s = 128; s > 0; s >>= 1) {
        if (tid < s) red[tid] += red[tid + s];
        __syncthreads();
    }
    float z = red[0] + b_beta[0];
    float beta = 1.f / (1.f + __expf(-z));

    float* ph = h + (size_t)row * DDIM;
    for (int i = tid; i < DDIM; i += 256)
        ph[i] = rna_tf32(beta * sx[i] + (1.f - beta) * sa[i]);
}

// ---------------------------------------------------------------------------
extern "C" void kernel_launch(void* const* d_in, const int* in_sizes, int n_in,
                              void* d_out, int out_size)
{
    const float* x      = (const float*)d_in[0];
    const float* W_skip = (const float*)d_in[1];
    const float* b_skip = (const float*)d_in[2];
    const float* W_q    = (const float*)d_in[3];
    const float* b_q    = (const float*)d_in[4];
    const float* W_k    = (const float*)d_in[5];
    const float* b_k    = (const float*)d_in[6];
    const float* W_v    = (const float*)d_in[7];
    const float* b_v    = (const float*)d_in[8];
    const float* W_beta = (const float*)d_in[9];
    const float* b_beta = (const float*)d_in[10];
    const float* W_fc   = (const float*)d_in[11];
    const float* b_fc   = (const float*)d_in[12];
    float* out = (float*)d_out;

    float *p, *vt, *a, *h, *s, *rx, *wcT, *wfT, *bc, *inv;
    cudaGetSymbolAddress((void**)&p,   g_p);
    cudaGetSymbolAddress((void**)&vt,  g_vt);
    cudaGetSymbolAddress((void**)&a,   g_a);
    cudaGetSymbolAddress((void**)&h,   g_h);
    cudaGetSymbolAddress((void**)&s,   g_s);
    cudaGetSymbolAddress((void**)&rx,  g_rx);
    cudaGetSymbolAddress((void**)&wcT, g_wcT);
    cudaGetSymbolAddress((void**)&wfT, g_wfT);
    cudaGetSymbolAddress((void**)&bc,  g_bc);
    cudaGetSymbolAddress((void**)&inv, g_inv);

    cudaFuncSetAttribute((const void*)gemm_cg2<true,  false>,
                         cudaFuncAttributeMaxDynamicSharedMemorySize, C2_SMEM);
    cudaFuncSetAttribute((const void*)gemm_cg2<false, false>,
                         cudaFuncAttributeMaxDynamicSharedMemorySize, C2_SMEM);
    cudaFuncSetAttribute((const void*)gemm_cg2<false, true>,
                         cudaFuncAttributeMaxDynamicSharedMemorySize, C2_SMEM);

    const int nd = NROWS * DDIM;

    // ---- prep ----
    round_copy<<<(nd / 4 + 255) / 256, 256>>>(x, rx, nd);
    dim3 tb(256);
    dim3 tgW(32, 32);
    transpose_rna<<<tgW, tb>>>(W_skip, DDIM, wcT + 0 * DDIM * DDIM, DDIM, DDIM, DDIM);
    transpose_rna<<<tgW, tb>>>(W_q,    DDIM, wcT + 1 * DDIM * DDIM, DDIM, DDIM, DDIM);
    transpose_rna<<<tgW, tb>>>(W_k,    DDIM, wcT + 2 * DDIM * DDIM, DDIM, DDIM, DDIM);
    transpose_rna<<<tgW, tb>>>(W_v,    DDIM, wcT + 3 * DDIM * DDIM, DDIM, DDIM, DDIM);
    transpose_rna<<<tgW, tb>>>(W_fc,   CDIM, wfT, DDIM, CDIM, DDIM);   // pad rows to 1024
    concat_bias<<<(NPROJ + 255) / 256, 256>>>(b_skip, b_q, b_k, b_v);
    prep_beta<<<(DDIM + 255) / 256, 256>>>(W_beta);

    // ---- fused projections: p[8192,4096] = rx @ wcT^T + bc (tf32-rounded) ----
    {
        dim3 g(2 * (NPROJ / 256), NROWS / 256);
        gemm_cg2<true, false><<<g, 256, C2_SMEM>>>(
            rx, DDIM, wcT, DDIM, bc, nullptr, p, NPROJ, DDIM, NPROJ, 1.f);
    }

    // ---- v^T (from packed p, strided) ----
    {
        dim3 g(DDIM / 32, NROWS / 32);
        transpose_rna<<<g, tb>>>(p + 3 * DDIM, NPROJ, vt, NROWS, DDIM, DDIM);
    }

    // ---- scores = q @ k^T / 32 ----
    {
        dim3 g(2 * (NROWS / 256), NROWS / 256);
        gemm_cg2<false, false><<<g, 256, C2_SMEM>>>(
            p + 1 * DDIM, NPROJ, p + 2 * DDIM, NPROJ, nullptr, nullptr,
            s, NROWS, DDIM, NROWS, 0.03125f);
    }

    // ---- exp (unnormalized, tf32) + 1/rowsum ----
    exp_rows<<<NROWS, 256>>>(s, NROWS);

    // ---- a = (expS @ v) * inv_rowsum ----
    {
        dim3 g(2 * (DDIM / 256), NROWS / 256);
        gemm_cg2<false, true><<<g, 256, C2_SMEM>>>(
            s, NROWS, vt, NROWS, nullptr, inv, a, DDIM, NROWS, DDIM, 1.f);
    }

    // ---- h = beta*x_r + (1-beta)*a ----
    beta_gate<<<NROWS, 256>>>(a, p, NPROJ, b_beta, h);

    // ---- out = h @ W_fc + b_fc (wfT padded; store-guarded to 1000) ----
    {
        dim3 g(2 * (DDIM / 256), NROWS / 256);
        gemm_cg2<false, false><<<g, 256, C2_SMEM>>>(
            h, DDIM, wfT, DDIM, b_fc, nullptr, out, CDIM, DDIM, CDIM, 1.f);
    }
}

// round 9
// speedup vs baseline: 11.9845x; 1.2663x over previous
#include <cuda_runtime.h>
#include <cstdint>
#include <cstddef>

#define NROWS 8192
#define DDIM  1024
#define CDIM  1000
#define NPROJ 4096   // skip|q|k|v packed
#define NTILE 512    // cluster N-tile
#define QKTILES (NROWS / NTILE)   // 16 col-tiles in QK

#if defined(__CUDA_ARCH_FEAT_SM103_ALL) || defined(__CUDA_ARCH_FEAT_SM100_ALL) || defined(__CUDA_ARCH_FEAT_SM101_ALL)
#define HAS_TCGEN05 1
#else
#define HAS_TCGEN05 0
#endif

// cg2 GEMM: cluster tile 256x512; per CTA: A 128 rows + B 256 rows (N-split)
#define NST  3
#define C2_A_BYTES 16384
#define C2_B_BYTES 32768
#define C2_STAGE   (C2_A_BYTES + C2_B_BYTES)     // 48 KB
#define C2_SMEM    (NST * C2_STAGE + 1024)       // 145 KB + pad

// ---------------- scratch (static device globals; no allocations) ----------
__device__ float g_p   [(size_t)NROWS * NPROJ];  // packed skip|q|k|v
__device__ float g_vt  [(size_t)DDIM * NROWS];
__device__ float g_a   [(size_t)NROWS * DDIM];
__device__ float g_h   [(size_t)NROWS * DDIM];
__device__ float g_s   [(size_t)NROWS * NROWS];  // 268 MB exp(scores)
__device__ float g_rx  [(size_t)NROWS * DDIM];
__device__ float g_wcT [(size_t)NPROJ * DDIM];   // concat(Wskip,Wq,Wk,Wv)^T
__device__ float g_wfT [(size_t)DDIM * DDIM];    // W_fc^T padded to 1024 rows
__device__ float g_bc  [NPROJ];
__device__ float g_part[(size_t)NROWS * QKTILES];// per-tile row sums (deterministic)
__device__ float g_inv [NROWS];                  // 1/rowsum(exp)
__device__ float g_u   [DDIM];
__device__ float g_w   [DDIM];

// ---------------- generic helpers -------------------------------------------
__device__ __forceinline__ float rna_tf32(float x) {
    uint32_t u;
    asm("cvt.rna.tf32.f32 %0, %1;" : "=r"(u) : "f"(x));
    return __uint_as_float(u);
}
__device__ __forceinline__ void cp16(uint32_t s, const void* g) {
    asm volatile("cp.async.cg.shared.global [%0], [%1], 16;\n" :: "r"(s), "l"(g));
}
__device__ __forceinline__ void cp_commit() { asm volatile("cp.async.commit_group;\n"); }
template<int Ng> __device__ __forceinline__ void cp_waitg() {
    asm volatile("cp.async.wait_group %0;\n" :: "n"(Ng));
}
__device__ __forceinline__ uint32_t sw128(uint32_t off) { return off ^ ((off >> 3) & 0x70); }
__device__ __forceinline__ uint32_t s2u(const void* p) {
    return (uint32_t)__cvta_generic_to_shared(p);
}

// ---------------- tcgen05/cluster helpers (guarded) --------------------------
__device__ __forceinline__ bool elect1() {
#if HAS_TCGEN05
    uint32_t p;
    asm volatile("{\n\t.reg .pred P;\n\telect.sync _|P, 0xFFFFFFFF;\n\t"
                 "selp.b32 %0, 1, 0, P;\n\t}" : "=r"(p));
    return p != 0;
#else
    return false;
#endif
}
__device__ __forceinline__ void mbar_init(uint32_t a, uint32_t c) {
    asm volatile("mbarrier.init.shared.b64 [%0], %1;" :: "r"(a), "r"(c) : "memory");
}
__device__ __forceinline__ void mbar_wait(uint32_t a, uint32_t parity) {
    asm volatile(
        "{\n\t.reg .pred P;\n\t"
        "W_%=:\n\t"
        "mbarrier.try_wait.parity.acquire.cta.shared::cta.b64 P, [%0], %1, 0x989680;\n\t"
        "@P bra.uni D_%=;\n\t"
        "bra.uni W_%=;\n\t"
        "D_%=:\n\t}"
        :: "r"(a), "r"(parity) : "memory");
}
__device__ __forceinline__ void mbar_wait_cluster(uint32_t a, uint32_t parity) {
#if HAS_TCGEN05
    asm volatile(
        "{\n\t.reg .pred P;\n\t"
        "W_%=:\n\t"
        "mbarrier.try_wait.parity.acquire.cluster.shared::cta.b64 P, [%0], %1, 0x989680;\n\t"
        "@P bra.uni D_%=;\n\t"
        "bra.uni W_%=;\n\t"
        "D_%=:\n\t}"
        :: "r"(a), "r"(parity) : "memory");
#endif
}
__device__ __forceinline__ void arrive_rank0(uint32_t local_addr) {
#if HAS_TCGEN05
    asm volatile(
        "{\n\t.reg .b32 ra;\n\t"
        "mapa.shared::cluster.u32 ra, %0, 0;\n\t"
        "mbarrier.arrive.shared::cluster.b64 _, [ra];\n\t}"
        :: "r"(local_addr) : "memory");
#endif
}
__device__ __forceinline__ void cluster_sync() {
#if HAS_TCGEN05
    asm volatile("barrier.cluster.arrive.aligned;" ::: "memory");
    asm volatile("barrier.cluster.wait.aligned;" ::: "memory");
#endif
}
__device__ __forceinline__ uint64_t sdesc(uint32_t addr) {
    return ((uint64_t)2 << 61) | ((uint64_t)1 << 46) | ((uint64_t)64 << 32)
         | ((uint64_t)1 << 16) | ((addr >> 4) & 0x3FFF);
}
__device__ __forceinline__ void mma_tf32_cg2(uint32_t d, uint64_t ad, uint64_t bd,
                                             uint32_t idesc, uint32_t en) {
#if HAS_TCGEN05
    asm volatile(
        "{\n\t.reg .pred p;\n\tsetp.ne.u32 p, %4, 0;\n\t"
        "tcgen05.mma.cta_group::2.kind::tf32 [%0], %1, %2, %3, "
        "{%5,%5,%5,%5,%5,%5,%5,%5}, p;\n\t}"
        :: "r"(d), "l"(ad), "l"(bd), "r"(idesc), "r"(en), "r"(0u) : "memory");
#endif
}
__device__ __forceinline__ void commit_mc2(uint32_t mbar) {
#if HAS_TCGEN05
    asm volatile(
        "tcgen05.commit.cta_group::2.mbarrier::arrive::one.shared::cluster"
        ".multicast::cluster.b64 [%0], %1;"
        :: "r"(mbar), "h"((uint16_t)0x3) : "memory");
#endif
}
__device__ __forceinline__ void ldtm32(uint32_t* r, uint32_t addr) {
#if HAS_TCGEN05
    asm volatile(
        "tcgen05.ld.sync.aligned.32x32b.x32.b32 "
        "{%0,%1,%2,%3,%4,%5,%6,%7,%8,%9,%10,%11,%12,%13,%14,%15,"
        "%16,%17,%18,%19,%20,%21,%22,%23,%24,%25,%26,%27,%28,%29,%30,%31}, [%32];"
        : "=r"(r[0]),  "=r"(r[1]),  "=r"(r[2]),  "=r"(r[3]),
          "=r"(r[4]),  "=r"(r[5]),  "=r"(r[6]),  "=r"(r[7]),
          "=r"(r[8]),  "=r"(r[9]),  "=r"(r[10]), "=r"(r[11]),
          "=r"(r[12]), "=r"(r[13]), "=r"(r[14]), "=r"(r[15]),
          "=r"(r[16]), "=r"(r[17]), "=r"(r[18]), "=r"(r[19]),
          "=r"(r[20]), "=r"(r[21]), "=r"(r[22]), "=r"(r[23]),
          "=r"(r[24]), "=r"(r[25]), "=r"(r[26]), "=r"(r[27]),
          "=r"(r[28]), "=r"(r[29]), "=r"(r[30]), "=r"(r[31])
        : "r"(addr));
#endif
}

// ---------------- cg2 tcgen05 TF32 GEMM (NT), 256x512 cluster tile -----------
// C = alpha*(A[M,K] @ B[N,K]^T) with epilogue MODE:
//   0: +bias               1: +bias, tf32-round out
//   2: exp(v)->tf32, write row-partial sums to g_part   3: *g_inv[row]
// grid = (2*N/512, M/256), cluster (2,1,1). M%256==0, N%512==0, K%32==0.
template<int MODE>
__global__ __launch_bounds__(256, 1) __cluster_dims__(2, 1, 1)
void gemm_cg2(const float* __restrict__ A, int lda,
              const float* __restrict__ B, int ldb,
              const float* __restrict__ bias,
              float* __restrict__ C, int ldc, int K, int Nstore, float alpha)
{
#if HAS_TCGEN05
    extern __shared__ char dsm[];
    __shared__ uint32_t s_tmem;
    __shared__ __align__(8) uint64_t s_full[NST];
    __shared__ __align__(8) uint64_t s_done[NST];
    __shared__ float sred[2][128];

    const int tid  = threadIdx.x;
    const int lane = tid & 31;
    const int wid  = tid >> 5;
    uint32_t rank;
    asm("mov.u32 %0, %%cluster_ctarank;" : "=r"(rank));

    const int col0  = (blockIdx.x >> 1) * NTILE;
    const int row0  = blockIdx.y * 256;
    const int aRow0 = row0 + (int)rank * 128;

    const uint32_t base = (s2u(dsm) + 1023u) & ~1023u;

    if (tid == 0) {
#pragma unroll
        for (int i = 0; i < NST; i++) {
            mbar_init(s2u(&s_full[i]), 2);
            mbar_init(s2u(&s_done[i]), 1);
        }
    }
    if (wid == 0) {
        asm volatile("tcgen05.alloc.cta_group::2.sync.aligned.shared::cta.b32 [%0], %1;"
                     :: "r"(s2u(&s_tmem)), "r"(512u) : "memory");
    }
    __syncthreads();
    cluster_sync();
    const uint32_t tmem = s_tmem;

    // idesc: F32 acc, tf32 a/b, N=256 per dispatch, M=256 (cg2)
    const uint32_t idesc = (1u << 4) | (2u << 7) | (2u << 10)
                         | ((256 / 8) << 17) | ((256 / 16) << 24);

    const int stages = K / 32;

    auto load_stage = [&](int s) {
        const int buf = s % NST;
        const int k0  = s * 32;
        const uint32_t ab = base + buf * C2_STAGE;
        const uint32_t bb = ab + C2_A_BYTES;
        // A: this CTA's 128 M-rows x 128 B
#pragma unroll
        for (int it = 0; it < 4; it++) {
            int idx = tid + it * 256;
            int r = idx >> 3, cb = idx & 7;
            cp16(ab + sw128(r * 128 + cb * 16),
                 A + (size_t)(aRow0 + r) * lda + k0 + cb * 4);
        }
        // B: 256 local rows; rows [0,128) serve MMA#1, [128,256) MMA#2.
        // global N index = col0 + (j>>7)*256 + rank*128 + (j&127)
#pragma unroll
        for (int it = 0; it < 8; it++) {
            int idx = tid + it * 256;
            int j = idx >> 3, cb = idx & 7;
            int g = col0 + ((j >> 7) << 8) + (int)rank * 128 + (j & 127);
            cp16(bb + sw128(j * 128 + cb * 16),
                 B + (size_t)g * ldb + k0 + cb * 4);
        }
        cp_commit();
    };

    load_stage(0);
    if (stages > 1) load_stage(1);

    for (int s = 0; s < stages; s++) {
        if (s + 1 < stages) cp_waitg<1>();
        else                cp_waitg<0>();
        __syncthreads();

        if (tid == 0) {
            asm volatile("fence.proxy.async.shared::cta;" ::: "memory");
            arrive_rank0(s2u(&s_full[s % NST]));
        }

        if (rank == 0 && wid == 0) {
            if (elect1()) {
                mbar_wait_cluster(s2u(&s_full[s % NST]),
                                  (uint32_t)((s / NST) & 1));
                const uint32_t ab = base + (s % NST) * C2_STAGE;
                const uint64_t ad = sdesc(ab);
                const uint64_t bd = sdesc(ab + C2_A_BYTES);
#pragma unroll
                for (int ks = 0; ks < 4; ks++) {
                    uint32_t en = (s > 0 || ks > 0) ? 1u : 0u;
                    mma_tf32_cg2(tmem,       ad + 2 * ks, bd + 2 * ks,        idesc, en);
                    mma_tf32_cg2(tmem + 256, ad + 2 * ks, bd + 2 * ks + 1024, idesc, en);
                }
                commit_mc2(s2u(&s_done[s % NST]));
            }
        }

        const int t = s + 2;
        if (t < stages) {
            if (s >= 1) mbar_wait(s2u(&s_done[(s - 1) % NST]),
                                  (uint32_t)(((s - 1) / NST) & 1));
            load_stage(t);
        }
    }

    mbar_wait(s2u(&s_done[(stages - 1) % NST]),
              (uint32_t)(((stages - 1) / NST) & 1));
    asm volatile("tcgen05.fence::after_thread_sync;" ::: "memory");

    // epilogue: this CTA's 128 rows x 512 cols.
    // warps 0-3: tmem cols [0,256); warps 4-7: [256,512). rows: (wid&3)*32+lane
    {
        const int sub = wid & 3;
        const int half = wid >> 2;
        const int colBase = half * 256;
        const int r = aRow0 + sub * 32 + lane;
        float scale = alpha;
        if (MODE == 3) scale *= g_inv[r];
        float rowsum = 0.f;
        uint32_t d[32];
#pragma unroll
        for (int cb = 0; cb < 8; cb++) {
            ldtm32(d, tmem + colBase + cb * 32);
            asm volatile("tcgen05.wait::ld.sync.aligned;" ::: "memory");
            const int c0 = col0 + colBase + cb * 32;
            float* cp = C + (size_t)r * ldc + c0;
            if (c0 + 31 < Nstore) {
#pragma unroll
                for (int j = 0; j < 32; j += 4) {
                    float4 v;
                    v.x = scale * __uint_as_float(d[j + 0]);
                    v.y = scale * __uint_as_float(d[j + 1]);
                    v.z = scale * __uint_as_float(d[j + 2]);
                    v.w = scale * __uint_as_float(d[j + 3]);
                    if (MODE == 0 || MODE == 1) {
                        v.x += bias[c0 + j + 0]; v.y += bias[c0 + j + 1];
                        v.z += bias[c0 + j + 2]; v.w += bias[c0 + j + 3];
                    }
                    if (MODE == 2) {
                        v.x = rna_tf32(__expf(v.x)); v.y = rna_tf32(__expf(v.y));
                        v.z = rna_tf32(__expf(v.z)); v.w = rna_tf32(__expf(v.w));
                        rowsum += v.x + v.y + v.z + v.w;
                    }
                    if (MODE == 1) {
                        v.x = rna_tf32(v.x); v.y = rna_tf32(v.y);
                        v.z = rna_tf32(v.z); v.w = rna_tf32(v.w);
                    }
                    *(float4*)(cp + j) = v;
                }
            } else {
#pragma unroll
                for (int j = 0; j < 32; j++) {
                    if (c0 + j < Nstore) {
                        float v = scale * __uint_as_float(d[j]);
                        if (MODE == 0 || MODE == 1) v += bias[c0 + j];
                        if (MODE == 2) { v = rna_tf32(__expf(v)); rowsum += v; }
                        if (MODE == 1) v = rna_tf32(v);
                        cp[j] = v;
                    }
                }
            }
        }
        asm volatile("tcgen05.fence::before_thread_sync;" ::: "memory");

        if (MODE == 2) {
            sred[half][sub * 32 + lane] = rowsum;
            __syncthreads();
            if (tid < 128) {
                float tot = sred[0][tid] + sred[1][tid];
                g_part[(size_t)(aRow0 + tid) * QKTILES + (col0 >> 9)] = tot;
            }
        }
    }

    __syncthreads();
    if (wid == 0) {
        asm volatile("tcgen05.relinquish_alloc_permit.cta_group::2.sync.aligned;");
        asm volatile("tcgen05.dealloc.cta_group::2.sync.aligned.b32 %0, %1;"
                     :: "r"(tmem), "r"(512u));
    }
    cluster_sync();
#endif  // HAS_TCGEN05
}

// ---------------- invert row sums -------------------------------------------
__global__ void invert_sums()
{
    int r = blockIdx.x * 256 + threadIdx.x;
    if (r < NROWS) {
        float s = 0.f;
#pragma unroll
        for (int t = 0; t < QKTILES; t++) s += g_part[(size_t)r * QKTILES + t];
        g_inv[r] = 1.f / s;
    }
}

// ---------------- tiled transpose + tf32 round (+row pad with zeros) --------
__global__ __launch_bounds__(256) void transpose_rna(
    const float* __restrict__ in, int in_ld, float* __restrict__ out,
    int R, int C, int outR)
{
    __shared__ float t[32][33];
    const int bx = blockIdx.x * 32;
    const int by = blockIdx.y * 32;
    const int x = threadIdx.x & 31;
    const int y = threadIdx.x >> 5;
#pragma unroll
    for (int dy = 0; dy < 4; dy++) {
        int r = by + y + dy * 8, c = bx + x;
        t[y + dy * 8][x] = (c < C) ? in[(size_t)r * in_ld + c] : 0.f;
    }
    __syncthreads();
#pragma unroll
    for (int dy = 0; dy < 4; dy++) {
        int c = bx + y + dy * 8, r = by + x;
        if (c < outR) out[(size_t)c * R + r] = rna_tf32(t[x][y + dy * 8]);
    }
}

// ---------------- elementwise prep ------------------------------------------
__global__ void round_copy(const float* __restrict__ s, float* __restrict__ d, int n)
{
    int i = (blockIdx.x * 256 + threadIdx.x) * 4;
    if (i < n) {
        float4 v = *(const float4*)(s + i);
        v.x = rna_tf32(v.x); v.y = rna_tf32(v.y);
        v.z = rna_tf32(v.z); v.w = rna_tf32(v.w);
        *(float4*)(d + i) = v;
    }
}
__global__ void concat_bias(const float* __restrict__ bs, const float* __restrict__ bq,
                            const float* __restrict__ bk, const float* __restrict__ bv)
{
    int i = blockIdx.x * 256 + threadIdx.x;
    if (i < NPROJ) {
        int sec = i >> 10, c = i & 1023;
        g_bc[i] = (sec == 0) ? bs[c] : (sec == 1) ? bq[c] : (sec == 2) ? bk[c] : bv[c];
    }
}
__global__ void prep_beta(const float* __restrict__ Wb)
{
    int i = blockIdx.x * 256 + threadIdx.x;
    if (i < DDIM) {
        g_u[i] = Wb[i] + Wb[2 * DDIM + i];
        g_w[i] = Wb[DDIM + i] - Wb[2 * DDIM + i];
    }
}

// ---------------- fused beta + gate: h = beta*x_r + (1-beta)*a (tf32 out) ---
__global__ __launch_bounds__(256) void beta_gate(
    const float* __restrict__ a, const float* __restrict__ xr, int xld,
    const float* __restrict__ b_beta, float* __restrict__ h)
{
    __shared__ float sa[DDIM];
    __shared__ float sx[DDIM];
    __shared__ float red[256];
    const int row = blockIdx.x;
    const int tid = threadIdx.x;
    const float* pa = a  + (size_t)row * DDIM;
    const float* px = xr + (size_t)row * xld;

    float part = 0.f;
    for (int i = tid; i < DDIM; i += 256) {
        float av = pa[i], xv = px[i];
        sa[i] = av; sx[i] = xv;
        part += av * g_u[i] + xv * g_w[i];
    }
    red[tid] = part; __syncthreads();
    for (int s = 128; s > 0; s >>= 1) {
        if (tid < s) red[tid] += red[tid + s];
        __syncthreads();
    }
    float z = red[0] + b_beta[0];
    float beta = 1.f / (1.f + __expf(-z));

    float* ph = h + (size_t)row * DDIM;
    for (int i = tid; i < DDIM; i += 256)
        ph[i] = rna_tf32(beta * sx[i] + (1.f - beta) * sa[i]);
}

// ---------------------------------------------------------------------------
extern "C" void kernel_launch(void* const* d_in, const int* in_sizes, int n_in,
                              void* d_out, int out_size)
{
    const float* x      = (const float*)d_in[0];
    const float* W_skip = (const float*)d_in[1];
    const float* b_skip = (const float*)d_in[2];
    const float* W_q    = (const float*)d_in[3];
    const float* b_q    = (const float*)d_in[4];
    const float* W_k    = (const float*)d_in[5];
    const float* b_k    = (const float*)d_in[6];
    const float* W_v    = (const float*)d_in[7];
    const float* b_v    = (const float*)d_in[8];
    const float* W_beta = (const float*)d_in[9];
    const float* b_beta = (const float*)d_in[10];
    const float* W_fc   = (const float*)d_in[11];
    const float* b_fc   = (const float*)d_in[12];
    float* out = (float*)d_out;

    float *p, *vt, *a, *h, *s, *rx, *wcT, *wfT, *bc;
    cudaGetSymbolAddress((void**)&p,   g_p);
    cudaGetSymbolAddress((void**)&vt,  g_vt);
    cudaGetSymbolAddress((void**)&a,   g_a);
    cudaGetSymbolAddress((void**)&h,   g_h);
    cudaGetSymbolAddress((void**)&s,   g_s);
    cudaGetSymbolAddress((void**)&rx,  g_rx);
    cudaGetSymbolAddress((void**)&wcT, g_wcT);
    cudaGetSymbolAddress((void**)&wfT, g_wfT);
    cudaGetSymbolAddress((void**)&bc,  g_bc);

    cudaFuncSetAttribute((const void*)gemm_cg2<0>,
                         cudaFuncAttributeMaxDynamicSharedMemorySize, C2_SMEM);
    cudaFuncSetAttribute((const void*)gemm_cg2<1>,
                         cudaFuncAttributeMaxDynamicSharedMemorySize, C2_SMEM);
    cudaFuncSetAttribute((const void*)gemm_cg2<2>,
                         cudaFuncAttributeMaxDynamicSharedMemorySize, C2_SMEM);
    cudaFuncSetAttribute((const void*)gemm_cg2<3>,
                         cudaFuncAttributeMaxDynamicSharedMemorySize, C2_SMEM);

    const int nd = NROWS * DDIM;

    // ---- prep ----
    round_copy<<<(nd / 4 + 255) / 256, 256>>>(x, rx, nd);
    dim3 tb(256);
    dim3 tgW(32, 32);
    transpose_rna<<<tgW, tb>>>(W_skip, DDIM, wcT + 0 * DDIM * DDIM, DDIM, DDIM, DDIM);
    transpose_rna<<<tgW, tb>>>(W_q,    DDIM, wcT + 1 * DDIM * DDIM, DDIM, DDIM, DDIM);
    transpose_rna<<<tgW, tb>>>(W_k,    DDIM, wcT + 2 * DDIM * DDIM, DDIM, DDIM, DDIM);
    transpose_rna<<<tgW, tb>>>(W_v,    DDIM, wcT + 3 * DDIM * DDIM, DDIM, DDIM, DDIM);
    transpose_rna<<<tgW, tb>>>(W_fc,   CDIM, wfT, DDIM, CDIM, DDIM);
    concat_bias<<<(NPROJ + 255) / 256, 256>>>(b_skip, b_q, b_k, b_v);
    prep_beta<<<(DDIM + 255) / 256, 256>>>(W_beta);

    // ---- fused projections: p = rx @ wcT^T + bc (tf32-rounded) ----
    {
        dim3 g(2 * (NPROJ / NTILE), NROWS / 256);
        gemm_cg2<1><<<g, 256, C2_SMEM>>>(rx, DDIM, wcT, DDIM, bc,
                                         p, NPROJ, DDIM, NPROJ, 1.f);
    }

    // ---- v^T (from packed p, strided) ----
    {
        dim3 g(DDIM / 32, NROWS / 32);
        transpose_rna<<<g, tb>>>(p + 3 * DDIM, NPROJ, vt, NROWS, DDIM, DDIM);
    }

    // ---- S = exp(q @ k^T / 32), tf32; per-tile row sums to g_part ----
    {
        dim3 g(2 * (NROWS / NTILE), NROWS / 256);
        gemm_cg2<2><<<g, 256, C2_SMEM>>>(p + 1 * DDIM, NPROJ, p + 2 * DDIM, NPROJ,
                                         nullptr, s, NROWS, DDIM, NROWS, 0.03125f);
    }

    // ---- 1/rowsum ----
    invert_sums<<<NROWS / 256, 256>>>();

    // ---- a = (S @ v) * inv[row] ----
    {
        dim3 g(2 * (DDIM / NTILE), NROWS / 256);
        gemm_cg2<3><<<g, 256, C2_SMEM>>>(s, NROWS, vt, NROWS, nullptr,
                                         a, DDIM, NROWS, DDIM, 1.f);
    }

    // ---- h = beta*x_r + (1-beta)*a ----
    beta_gate<<<NROWS, 256>>>(a, p, NPROJ, b_beta, h);

    // ---- out = h @ W_fc + b_fc (padded to 1024; store-guarded to 1000) ----
    {
        dim3 g(2 * (DDIM / NTILE), NROWS / 256);
        gemm_cg2<0><<<g, 256, C2_SMEM>>>(h, DDIM, wfT, DDIM, b_fc,
                                         out, CDIM, DDIM, CDIM, 1.f);
    }
}